// round 15
// baseline (speedup 1.0000x reference)
#include <cuda_runtime.h>
#include <cuda_fp16.h>
#include <cstdint>

#define Bv 4
#define Sv 2048
#define Ev 512
#define Hv 8
#define HEv 4096
#define EEv 262144

// fp32 scratch
__device__ float g_T[(long)Bv * Hv * EEv];     // split-K partials (32 MB, nsplit<=8)
__device__ float g_ksum[Bv * Ev], g_vsum[Bv * Ev];
__device__ float g_cspart[2 * Bv * 16 * Ev];
__device__ float g_pp[32 * 8 * Ev];
__device__ float g_a[Bv * Hv * Ev], g_w[Bv * Hv * Ev];
__device__ float g_alpha[Bv * Hv * Ev], g_gamma[Hv * Ev];
__device__ float g_beta[Hv * Ev], g_delta[Bv * Hv * Ev];
__device__ float g_u[Hv * Ev], g_p[Bv * Hv * Ev], g_sigma[Bv * Hv * Ev];
__device__ float g_s1[Bv * Hv], g_s2[Hv];
__device__ float g_r[Bv * HEv], g_c[Bv * Ev];

// fp16 hi|lo buffers (lo at +half)
__device__ __half c_kT [2L * Bv * Ev * Sv];
__device__ __half c_vT [2L * Bv * Ev * Sv];
__device__ __half c_WqT[2L * Hv * EEv];
__device__ __half c_WkT[2L * Hv * EEv];
__device__ __half c_WvT[2L * Hv * EEv];
__device__ __half c_Wo [2L * Ev * HEv];
__device__ __half c_G  [2L * Bv * EEv];
__device__ __half c_U  [2L * Ev * HEv];
__device__ __half c_V  [2L * Hv * EEv];
__device__ __half c_X  [2L * Bv * Ev * HEv];
__device__ __half c_q  [2L * Bv * Sv * Ev];
__device__ __half c_NT [2L * Bv * EEv];

__device__ __forceinline__ uint32_t smem_u32(const void* p) {
    uint32_t a;
    asm("{ .reg .u64 t; cvta.to.shared.u64 t, %1; cvt.u32.u64 %0, t; }" : "=r"(a) : "l"(p));
    return a;
}
__device__ __forceinline__ void cpa16(uint32_t dst, const void* src) {
    asm volatile("cp.async.cg.shared.global [%0], [%1], 16;" :: "r"(dst), "l"(src));
}
__device__ __forceinline__ void ldsm4(uint32_t* r, uint32_t addr) {
    asm volatile("ldmatrix.sync.aligned.m8n8.x4.shared.b16 {%0,%1,%2,%3}, [%4];"
        : "=r"(r[0]), "=r"(r[1]), "=r"(r[2]), "=r"(r[3]) : "r"(addr));
}
__device__ __forceinline__ void mma_f16(float* d, const uint32_t* a, const uint32_t* b) {
    asm volatile("mma.sync.aligned.m16n8k16.row.col.f32.f16.f16.f32 "
        "{%0,%1,%2,%3}, {%4,%5,%6,%7}, {%8,%9}, {%0,%1,%2,%3};"
        : "+f"(d[0]), "+f"(d[1]), "+f"(d[2]), "+f"(d[3])
        : "r"(a[0]), "r"(a[1]), "r"(a[2]), "r"(a[3]), "r"(b[0]), "r"(b[1]));
}
__device__ __forceinline__ __half2 hl2(float x, float y) {
    __half2 r; r.x = __float2half(x); r.y = __float2half(y); return r;
}

#define STAGE 32768
#define SMEM_DYN (3 * STAGE)

// MODE: 0 = fp32 (split-K partials), 1 = fp32 + bias, 2 = fp16 hi/lo (aux = lo base)
template <int MODE>
__global__ void __launch_bounds__(128, 2)
tgemm(const __half* __restrict__ Ahi, const __half* __restrict__ Alo,
      const __half* __restrict__ Bhi, const __half* __restrict__ Blo,
      void* __restrict__ Cout, const void* __restrict__ aux,
      int K, int lda, int ldb, int ldc, int zmod,
      long aS1, long aS2, long bS1, long bS2, long cS1, long cS2,
      long auxStride, int nsplit, long partStride, int nterms)
{
    extern __shared__ __align__(128) char dsm[];
    uint32_t sbase = smem_u32(dsm);

    int tid = threadIdx.x, wid = tid >> 5, lane = tid & 31;
    int zPer = gridDim.z / nsplit;
    int split = blockIdx.z / zPer;
    int z = blockIdx.z % zPer;
    int zm = z % zmod, zd = z / zmod;
    Ahi += zm * aS1 + zd * aS2;  Alo += zm * aS1 + zd * aS2;
    Bhi += zm * bS1 + zd * bS2;  Blo += zm * bS1 + zd * bS2;
    int m0 = blockIdx.y * 128, n0 = blockIdx.x * 128;

    const int Ks = K / nsplit;
    const int CPP = Ks >> 6;
    const int NC = nterms * CPP;
    const int kofs = split * Ks;

    int srow = tid >> 3, scs = tid & 7;

    auto issue = [&](int c) {
        int phase = c / CPP;
        int kpos = kofs + ((c - phase * CPP) << 6);
        const __half* pa = (nterms >= 2 && phase == nterms - 1) ? Alo : Ahi;
        const __half* pb = (phase == 1 && nterms == 3) ? Blo : Bhi;
        uint32_t sb = sbase + (uint32_t)((c % 3) * STAGE);
        #pragma unroll
        for (int t = 0; t < 16; t++) {
            int isB = t >> 3;
            int row = srow + ((t & 7) << 4);
            const __half* src = isB
                ? pb + (long)(n0 + row) * ldb + kpos + (scs << 3)
                : pa + (long)(m0 + row) * lda + kpos + (scs << 3);
            uint32_t bo = (uint32_t)((row << 7) + (scs << 4));
            bo ^= (uint32_t)((row & 7) << 4);
            cpa16(sb + (uint32_t)(isB << 14) + bo, src);
        }
        asm volatile("cp.async.commit_group;" ::: "memory");
    };

    issue(0);
    issue(1);

    float acc[4][8][4] = {};
    int moff = (wid & 1) << 6;
    int noff = (wid >> 1) << 6;

    for (int c = 0; c < NC; c++) {
        if (c + 1 < NC) asm volatile("cp.async.wait_group 1;" ::: "memory");
        else            asm volatile("cp.async.wait_group 0;" ::: "memory");
        __syncthreads();
        if (c + 2 < NC) issue(c + 2);
        uint32_t sb = sbase + (uint32_t)((c % 3) * STAGE);

        #pragma unroll
        for (int ks = 0; ks < 4; ks++) {
            uint32_t afr[4][4];
            #pragma unroll
            for (int i = 0; i < 4; i++) {
                int row = moff + (i << 4) + (lane & 15);
                int colb = (ks << 5) + ((lane >> 4) << 4);
                uint32_t bo = (uint32_t)((row << 7) + colb) ^ (uint32_t)((row & 7) << 4);
                ldsm4(afr[i], sb + bo);
            }
            uint32_t bfr[8][2];
            #pragma unroll
            for (int j2 = 0; j2 < 4; j2++) {
                int row = noff + (j2 << 4) + ((lane >> 4) << 3) + (lane & 7);
                int colb = (ks << 5) + (((lane >> 3) & 1) << 4);
                uint32_t bo = (uint32_t)((row << 7) + colb) ^ (uint32_t)((row & 7) << 4);
                uint32_t r[4];
                ldsm4(r, sb + 16384u + bo);
                bfr[2 * j2][0] = r[0]; bfr[2 * j2][1] = r[1];
                bfr[2 * j2 + 1][0] = r[2]; bfr[2 * j2 + 1][1] = r[3];
            }
            #pragma unroll
            for (int i = 0; i < 4; i++)
                #pragma unroll
                for (int j = 0; j < 8; j++)
                    mma_f16(acc[i][j], afr[i], bfr[j]);
        }
    }

    int g = lane >> 2, t4 = lane & 3;
    if (MODE == 2) {
        __half* hi = (__half*)Cout + zm * cS1 + zd * cS2;
        __half* lo = (__half*)aux  + zm * cS1 + zd * cS2;
        #pragma unroll
        for (int i = 0; i < 4; i++) {
            int row0 = m0 + moff + (i << 4) + g;
            #pragma unroll
            for (int j = 0; j < 8; j++) {
                int col = n0 + noff + (j << 3) + (t4 << 1);
                #pragma unroll
                for (int rr = 0; rr < 2; rr++) {
                    long off = (long)(row0 + 8 * rr) * ldc + col;
                    float vx = acc[i][j][2 * rr], vy = acc[i][j][2 * rr + 1];
                    __half2 h = hl2(vx, vy);
                    __half2 l = hl2(vx - __half2float(h.x), vy - __half2float(h.y));
                    *reinterpret_cast<__half2*>(hi + off) = h;
                    *reinterpret_cast<__half2*>(lo + off) = l;
                }
            }
        }
    } else {
        float* C = (float*)Cout + zm * cS1 + zd * cS2 + (long)split * partStride;
        const float* bp = (MODE == 1) ? ((const float*)aux + zd * auxStride) : nullptr;
        #pragma unroll
        for (int i = 0; i < 4; i++) {
            int row0 = m0 + moff + (i << 4) + g;
            #pragma unroll
            for (int j = 0; j < 8; j++) {
                int col = n0 + noff + (j << 3) + (t4 << 1);
                float bx = 0.f, by = 0.f;
                if (MODE == 1) { float2 bb = *reinterpret_cast<const float2*>(bp + col); bx = bb.x; by = bb.y; }
                float2 o0 = make_float2(acc[i][j][0] + bx, acc[i][j][1] + by);
                float2 o1 = make_float2(acc[i][j][2] + bx, acc[i][j][3] + by);
                *reinterpret_cast<float2*>(&C[(long)row0 * ldc + col]) = o0;
                *reinterpret_cast<float2*>(&C[(long)(row0 + 8) * ldc + col]) = o1;
            }
        }
    }
}

__global__ void reduce_hl(const float* __restrict__ parts, long pstride, int nsplit,
                          __half* __restrict__ hi, __half* __restrict__ lo) {
    long i = ((long)blockIdx.x * blockDim.x + threadIdx.x) * 4;
    float4 s = *reinterpret_cast<const float4*>(parts + i);
    for (int p = 1; p < nsplit; p++) {
        float4 t = *reinterpret_cast<const float4*>(parts + p * pstride + i);
        s.x += t.x; s.y += t.y; s.z += t.z; s.w += t.w;
    }
    __half2 h0 = hl2(s.x, s.y), h1 = hl2(s.z, s.w);
    __half2 l0 = hl2(s.x - __half2float(h0.x), s.y - __half2float(h0.y));
    __half2 l1 = hl2(s.z - __half2float(h1.x), s.w - __half2float(h1.y));
    *reinterpret_cast<__half2*>(hi + i) = h0;
    *reinterpret_cast<__half2*>(hi + i + 2) = h1;
    *reinterpret_cast<__half2*>(lo + i) = l0;
    *reinterpret_cast<__half2*>(lo + i + 2) = l1;
}

__global__ void nt_epilogue(const float* __restrict__ parts, long pstride, int nsplit,
                            const float* __restrict__ alpha, const float* __restrict__ gamma,
                            const float* __restrict__ beta, const float* __restrict__ delta,
                            __half* __restrict__ hi, __half* __restrict__ lo) {
    long i = ((long)blockIdx.x * blockDim.x + threadIdx.x) * 4;
    int e = (int)(i & 511);
    int o3 = (int)((i >> 9) & 511);
    int b = (int)(i >> 18);
    float4 s = *reinterpret_cast<const float4*>(parts + i);
    for (int p = 1; p < nsplit; p++) {
        float4 t = *reinterpret_cast<const float4*>(parts + p * pstride + i);
        s.x += t.x; s.y += t.y; s.z += t.z; s.w += t.w;
    }
    #pragma unroll
    for (int h = 0; h < Hv; h++) {
        float be = beta[h * Ev + o3];
        float de = delta[(b * Hv + h) * Ev + o3];
        float4 al = *reinterpret_cast<const float4*>(alpha + (long)(b * Hv + h) * Ev + e);
        float4 ga = *reinterpret_cast<const float4*>(gamma + h * Ev + e);
        s.x += be * (al.x + (float)Sv * ga.x) + de * ga.x;
        s.y += be * (al.y + (float)Sv * ga.y) + de * ga.y;
        s.z += be * (al.z + (float)Sv * ga.z) + de * ga.z;
        s.w += be * (al.w + (float)Sv * ga.w) + de * ga.w;
    }
    const float invE = 1.0f / (float)Ev;
    s.x *= invE; s.y *= invE; s.z *= invE; s.w *= invE;
    __half2 h0 = hl2(s.x, s.y), h1 = hl2(s.z, s.w);
    __half2 l0 = hl2(s.x - __half2float(h0.x), s.y - __half2float(h0.y));
    __half2 l1 = hl2(s.z - __half2float(h1.x), s.w - __half2float(h1.y));
    *reinterpret_cast<__half2*>(hi + i) = h0;
    *reinterpret_cast<__half2*>(hi + i + 2) = h1;
    *reinterpret_cast<__half2*>(lo + i) = l0;
    *reinterpret_cast<__half2*>(lo + i + 2) = l1;
}

__global__ void conv_split(const float* __restrict__ src, __half* __restrict__ hi,
                           __half* __restrict__ lo) {
    long i = ((long)blockIdx.x * blockDim.x + threadIdx.x) * 4;
    float4 x = *reinterpret_cast<const float4*>(src + i);
    __half2 h0 = hl2(x.x, x.y), h1 = hl2(x.z, x.w);
    __half2 l0 = hl2(x.x - __half2float(h0.x), x.y - __half2float(h0.y));
    __half2 l1 = hl2(x.z - __half2float(h1.x), x.w - __half2float(h1.y));
    *reinterpret_cast<__half2*>(hi + i) = h0;
    *reinterpret_cast<__half2*>(hi + i + 2) = h1;
    *reinterpret_cast<__half2*>(lo + i) = l0;
    *reinterpret_cast<__half2*>(lo + i + 2) = l1;
}

// hi-only elementwise conversion (consumer is 1-term)
__global__ void conv_hi(const float* __restrict__ src, __half* __restrict__ hi) {
    long i = ((long)blockIdx.x * blockDim.x + threadIdx.x) * 4;
    float4 x = *reinterpret_cast<const float4*>(src + i);
    __half2 h0 = hl2(x.x, x.y), h1 = hl2(x.z, x.w);
    *reinterpret_cast<__half2*>(hi + i) = h0;
    *reinterpret_cast<__half2*>(hi + i + 2) = h1;
}

__global__ void conv_tsplit(const float* __restrict__ src, __half* __restrict__ hi,
                            __half* __restrict__ lo,
                            int srcLd, long srcZ, int dstLd, long dstZ, int wlo) {
    __shared__ float tile[32][33];
    int zz = blockIdx.z;
    src += (long)zz * srcZ;
    long dz = (long)zz * dstZ;
    int k0 = blockIdx.x * 32, r0 = blockIdx.y * 32;
    int tx = threadIdx.x, ty = threadIdx.y;
    #pragma unroll
    for (int i = 0; i < 4; i++)
        tile[ty + 8 * i][tx] = src[(long)(k0 + ty + 8 * i) * srcLd + r0 + tx];
    __syncthreads();
    #pragma unroll
    for (int i = 0; i < 4; i++) {
        int r = r0 + ty + 8 * i, kk = k0 + tx;
        float x = tile[tx][ty + 8 * i];
        __half h = __float2half(x);
        hi[dz + (long)r * dstLd + kk] = h;
        if (wlo) lo[dz + (long)r * dstLd + kk] = __float2half(x - __half2float(h));
    }
}

// merged k+v transpose (hi only): grid (64, 16, 8); z: b = zz&3, which = zz>>2
__global__ void conv_tkv(const float* __restrict__ k, const float* __restrict__ v,
                         __half* __restrict__ kT, __half* __restrict__ vT) {
    __shared__ float tile[32][33];
    int zz = blockIdx.z;
    int b = zz & 3, which = zz >> 2;
    const float* src = (which ? v : k) + (long)b * Sv * Ev;
    __half* dst = (which ? vT : kT) + (long)b * Ev * Sv;
    int k0 = blockIdx.x * 32, r0 = blockIdx.y * 32;
    int tx = threadIdx.x, ty = threadIdx.y;
    #pragma unroll
    for (int i = 0; i < 4; i++)
        tile[ty + 8 * i][tx] = src[(long)(k0 + ty + 8 * i) * Ev + r0 + tx];
    __syncthreads();
    #pragma unroll
    for (int i = 0; i < 4; i++)
        dst[(long)(r0 + ty + 8 * i) * Sv + k0 + tx] = __float2half(tile[tx][ty + 8 * i]);
}

// stage-1 column sums: grid (16, Bv, 2), block 512
__global__ void csum_part(const float* __restrict__ k, const float* __restrict__ v,
                          float* __restrict__ part) {
    int chunk = blockIdx.x, b = blockIdx.y, which = blockIdx.z, e = threadIdx.x;
    const float* src = (which ? v : k) + (long)b * Sv * Ev + (long)chunk * 128 * Ev + e;
    float s = 0.f;
    for (int i = 0; i < 128; i++) s += src[(long)i * Ev];
    part[(((long)which * Bv + b) * 16 + chunk) * Ev + e] = s;
}
__global__ void csum_final(const float* __restrict__ part, float* __restrict__ ks,
                           float* __restrict__ vs) {
    int b = blockIdx.x, which = blockIdx.y, e = threadIdx.x;
    const float* p = part + (((long)which * Bv + b) * 16) * Ev + e;
    float s = 0.f;
    #pragma unroll
    for (int i = 0; i < 16; i++) s += p[(long)i * Ev];
    (which ? vs : ks)[b * Ev + e] = s;
}

__global__ void rowdot_kernel(const float* __restrict__ W, const float* __restrict__ x,
                              float* __restrict__ out, int xsel) {
    int gw = (blockIdx.x * blockDim.x + threadIdx.x) >> 5, lane = threadIdx.x & 31;
    int o = gw & (Ev - 1), zz = gw >> 9;
    int h = zz & (Hv - 1);
    const float* wr = W + (long)(h * Ev + o) * Ev;
    const float* xr = x + (long)(xsel ? zz : (zz >> 3)) * Ev;
    float s = 0.f;
    for (int e = lane; e < Ev; e += 32) s += wr[e] * xr[e];
    #pragma unroll
    for (int off = 16; off > 0; off >>= 1) s += __shfl_xor_sync(0xFFFFFFFFu, s, off);
    if (lane == 0) out[gw] = s;
}

__global__ void rowdot_hl(const __half* __restrict__ Whi, const __half* __restrict__ Wlo,
                          const float* __restrict__ x, float* __restrict__ out) {
    int gw = (blockIdx.x * blockDim.x + threadIdx.x) >> 5, lane = threadIdx.x & 31;
    int e = gw & (Ev - 1), zz = gw >> 9;
    long wofs = (long)(zz & (Hv - 1)) * EEv + (long)e * Ev;
    const float* xr = x + (long)zz * Ev;
    float s = 0.f;
    for (int o = lane; o < Ev; o += 32)
        s += (__half2float(Whi[wofs + o]) + __half2float(Wlo[wofs + o])) * xr[o];
    #pragma unroll
    for (int off = 16; off > 0; off >>= 1) s += __shfl_xor_sync(0xFFFFFFFFu, s, off);
    if (lane == 0) out[gw] = s;
}

__global__ void rowdot_wo(const float* __restrict__ Wo, const float* __restrict__ x,
                          float* __restrict__ out) {
    int gw = (blockIdx.x * blockDim.x + threadIdx.x) >> 5, lane = threadIdx.x & 31;
    int o3 = gw & (Ev - 1), zz = gw >> 9;
    const float* wr = Wo + (long)o3 * HEv + (long)(zz & (Hv - 1)) * Ev;
    const float* xr = x + (long)zz * Ev;
    float s = 0.f;
    for (int e = lane; e < Ev; e += 32) s += wr[e] * xr[e];
    #pragma unroll
    for (int off = 16; off > 0; off >>= 1) s += __shfl_xor_sync(0xFFFFFFFFu, s, off);
    if (lane == 0) out[gw] = s;
}

__global__ void colmv_part(const __half* __restrict__ Ghi, const __half* __restrict__ Glo,
                           const float* __restrict__ u, float* __restrict__ pp) {
    int zz = blockIdx.x, chunk = blockIdx.y, tid = threadIdx.x;
    int b = zz >> 3, h = zz & (Hv - 1);
    __shared__ float us[64];
    if (tid < 64) us[tid] = u[h * Ev + chunk * 64 + tid];
    __syncthreads();
    const __half* gh = Ghi + (long)b * EEv + (long)chunk * 64 * Ev;
    const __half* gl = Glo + (long)b * EEv + (long)chunk * 64 * Ev;
    float acc = 0.f;
    #pragma unroll 4
    for (int i = 0; i < 64; i++) {
        long idx = (long)i * Ev + tid;
        acc += us[i] * (__half2float(gh[idx]) + __half2float(gl[idx]));
    }
    pp[((long)zz * 8 + chunk) * Ev + tid] = acc;
}
__global__ void colmv_final(const float* __restrict__ pp, float* __restrict__ p) {
    int idx = blockIdx.x * blockDim.x + threadIdx.x;
    int zz = idx >> 9, e = idx & (Ev - 1);
    const float* q = pp + (long)zz * 8 * Ev + e;
    float s = 0.f;
    #pragma unroll
    for (int i = 0; i < 8; i++) s += q[(long)i * Ev];
    p[idx] = s;
}

__global__ void dots_kernel(const float* __restrict__ bq, const float* __restrict__ a,
                            const float* __restrict__ bk,
                            float* __restrict__ s1, float* __restrict__ s2) {
    int gw = (blockIdx.x * blockDim.x + threadIdx.x) >> 5, lane = threadIdx.x & 31;
    if (gw >= 40) return;
    const float* xa;
    const float* xb;
    if (gw < 32) { xa = bq + (gw & 7) * Ev; xb = a + gw * Ev; }
    else         { xa = bq + (gw - 32) * Ev; xb = bk + (gw - 32) * Ev; }
    float s = 0.f;
    for (int o = lane; o < Ev; o += 32) s += xa[o] * xb[o];
    #pragma unroll
    for (int off = 16; off > 0; off >>= 1) s += __shfl_xor_sync(0xFFFFFFFFu, s, off);
    if (lane == 0) { if (gw < 32) s1[gw] = s; else s2[gw - 32] = s; }
}

__global__ void tau_kernel(const float* __restrict__ sigma, const float* __restrict__ s1,
                           const float* __restrict__ s2, const float* __restrict__ bv,
                           const float* __restrict__ w, float* __restrict__ tau) {
    int idx = blockIdx.x * blockDim.x + threadIdx.x;
    int zz = idx >> 9, o2 = idx & (Ev - 1), h = zz & (Hv - 1);
    float bvv = bv[h * Ev + o2];
    tau[idx] = sigma[idx] + s1[zz] * bvv + s2[h] * (w[idx] + (float)Sv * bvv);
}

__global__ void cvec_kernel(const float* __restrict__ r, const float* __restrict__ Wo,
                            const float* __restrict__ bo, float* __restrict__ c) {
    int gw = (blockIdx.x * blockDim.x + threadIdx.x) >> 5, lane = threadIdx.x & 31;
    int e2 = gw & (Ev - 1), b = gw >> 9;
    const float* rr = r + (long)b * HEv;
    const float* wr = Wo + (long)e2 * HEv;
    float s = 0.f;
    for (int f = lane; f < HEv; f += 32) s += rr[f] * wr[f];
    #pragma unroll
    for (int off = 16; off > 0; off >>= 1) s += __shfl_xor_sync(0xFFFFFFFFu, s, off);
    if (lane == 0) c[gw] = s * (1.0f / (float)Ev) + bo[e2];
}

extern "C" void kernel_launch(void* const* d_in, const int* in_sizes, int n_in,
                              void* d_out, int out_size) {
    const float* q  = (const float*)d_in[0];
    const float* k  = (const float*)d_in[1];
    const float* v  = (const float*)d_in[2];
    const float* Wq = (const float*)d_in[3];
    const float* bq = (const float*)d_in[4];
    const float* Wk = (const float*)d_in[5];
    const float* bk = (const float*)d_in[6];
    const float* Wv = (const float*)d_in[7];
    const float* bv = (const float*)d_in[8];
    const float* Wo = (const float*)d_in[9];
    const float* bo = (const float*)d_in[10];
    float* out = (float*)d_out;

    float *Tp, *ksum, *vsum, *cspart, *pp, *a, *w, *alpha, *gamma, *beta, *delta, *u, *p, *sigma, *s1, *s2, *r, *c;
    cudaGetSymbolAddress((void**)&Tp, g_T);
    cudaGetSymbolAddress((void**)&ksum, g_ksum);
    cudaGetSymbolAddress((void**)&vsum, g_vsum);
    cudaGetSymbolAddress((void**)&cspart, g_cspart);
    cudaGetSymbolAddress((void**)&pp, g_pp);
    cudaGetSymbolAddress((void**)&a, g_a);
    cudaGetSymbolAddress((void**)&w, g_w);
    cudaGetSymbolAddress((void**)&alpha, g_alpha);
    cudaGetSymbolAddress((void**)&gamma, g_gamma);
    cudaGetSymbolAddress((void**)&beta, g_beta);
    cudaGetSymbolAddress((void**)&delta, g_delta);
    cudaGetSymbolAddress((void**)&u, g_u);
    cudaGetSymbolAddress((void**)&p, g_p);
    cudaGetSymbolAddress((void**)&sigma, g_sigma);
    cudaGetSymbolAddress((void**)&s1, g_s1);
    cudaGetSymbolAddress((void**)&s2, g_s2);
    cudaGetSymbolAddress((void**)&r, g_r);
    cudaGetSymbolAddress((void**)&c, g_c);

    __half *kT, *vT, *bWqT, *bWkT, *bWvT, *bWo, *bG, *bU, *bV, *bX, *bq16, *bNT;
    cudaGetSymbolAddress((void**)&kT, c_kT);
    cudaGetSymbolAddress((void**)&vT, c_vT);
    cudaGetSymbolAddress((void**)&bWqT, c_WqT);
    cudaGetSymbolAddress((void**)&bWkT, c_WkT);
    cudaGetSymbolAddress((void**)&bWvT, c_WvT);
    cudaGetSymbolAddress((void**)&bWo, c_Wo);
    cudaGetSymbolAddress((void**)&bG, c_G);
    cudaGetSymbolAddress((void**)&bU, c_U);
    cudaGetSymbolAddress((void**)&bV, c_V);
    cudaGetSymbolAddress((void**)&bX, c_X);
    cudaGetSymbolAddress((void**)&bq16, c_q);
    cudaGetSymbolAddress((void**)&bNT, c_NT);

    static cudaStream_t sW = nullptr, sP = nullptr;
    static cudaEvent_t evRoot, evWc, evV, evWU, evG, evC;
    if (!sW) {
        cudaStreamCreateWithFlags(&sW, cudaStreamNonBlocking);
        cudaStreamCreateWithFlags(&sP, cudaStreamNonBlocking);
        cudaEventCreateWithFlags(&evRoot, cudaEventDisableTiming);
        cudaEventCreateWithFlags(&evWc, cudaEventDisableTiming);
        cudaEventCreateWithFlags(&evV, cudaEventDisableTiming);
        cudaEventCreateWithFlags(&evWU, cudaEventDisableTiming);
        cudaEventCreateWithFlags(&evG, cudaEventDisableTiming);
        cudaEventCreateWithFlags(&evC, cudaEventDisableTiming);
        cudaFuncSetAttribute(tgemm<0>, cudaFuncAttributeMaxDynamicSharedMemorySize, SMEM_DYN);
        cudaFuncSetAttribute(tgemm<1>, cudaFuncAttributeMaxDynamicSharedMemorySize, SMEM_DYN);
        cudaFuncSetAttribute(tgemm<2>, cudaFuncAttributeMaxDynamicSharedMemorySize, SMEM_DYN);
    }

    const long ES = (long)Ev * Sv, EE = EEv, SE = (long)Sv * Ev, EHE = (long)Ev * HEv;
    const long hKT = (long)Bv * ES, hW = (long)Hv * EEv, hWo = (long)Ev * HEv;
    const long hG = (long)Bv * EEv, hU = (long)Ev * HEv, hV = (long)Hv * EEv;
    const long hX = (long)Bv * Ev * HEv, hq = (long)Bv * SE, hNT = (long)Bv * EEv;
    const long PART = (long)Bv * EEv;

    dim3 tb(32, 8);

    cudaEventRecord(evRoot, 0);

    // ---- stream W: V first (2-term), then U (2-term) ----
    cudaStreamWaitEvent(sW, evRoot, 0);
    conv_tsplit<<<dim3(16, 16, Hv), tb, 0, sW>>>(Wv, bWvT, bWvT + hW, Ev, EE, Ev, EE, 1);
    conv_split<<<2048, 256, 0, sW>>>(Wo, bWo, bWo + hWo);
    tgemm<2><<<dim3(4, 4, Hv), 128, SMEM_DYN, sW>>>(
        bWo, bWo + hWo, bWvT, bWvT + hW, bV, bV + hV,
        Ev, HEv, Ev, Ev, Hv, (long)Ev, 0, EE, 0, EE, 0, 0, 1, 0, 2);
    cudaEventRecord(evV, sW);
    conv_tsplit<<<dim3(16, 16, Hv), tb, 0, sW>>>(Wq, bWqT, bWqT + hW, Ev, EE, Ev, EE, 1);
    conv_tsplit<<<dim3(16, 16, Hv), tb, 0, sW>>>(Wk, bWkT, bWkT + hW, Ev, EE, Ev, EE, 1);
    cudaEventRecord(evWc, sW);
    tgemm<2><<<dim3(4, 4, Hv), 128, SMEM_DYN, sW>>>(
        bWqT, bWqT + hW, bWkT, bWkT + hW, bU, bU + hU,
        Ev, Ev, Ev, HEv, Hv, EE, 0, EE, 0, (long)Ev, 0, 0, 1, 0, 2);
    cudaEventRecord(evWU, sW);

    // ---- stream P: fast parallel colsum, a/w, q conv (hi only) ----
    cudaStreamWaitEvent(sP, evRoot, 0);
    csum_part<<<dim3(16, Bv, 2), Ev, 0, sP>>>(k, v, cspart);
    csum_final<<<dim3(Bv, 2), Ev, 0, sP>>>(cspart, ksum, vsum);
    rowdot_kernel<<<2048, 256, 0, sP>>>(Wk, ksum, a, 0);
    rowdot_kernel<<<2048, 256, 0, sP>>>(Wv, vsum, w, 0);
    conv_hi<<<4096, 256, 0, sP>>>(q, bq16);

    // ---- main stream: merged k/v transpose (hi only), G (1-term, split-8) ----
    conv_tkv<<<dim3(64, 16, Bv * 2), tb>>>(k, v, kT, vT);
    tgemm<0><<<dim3(4, 4, Bv * 8), 128, SMEM_DYN>>>(
        kT, kT + hKT, vT, vT + hKT, Tp, nullptr,
        Sv, Sv, Sv, Ev, 1, 0, ES, 0, ES, 0, EE, 0, 8, PART, 1);
    reduce_hl<<<1024, 256>>>(Tp, PART, 8, bG, bG + hG);
    cudaEventRecord(evG, 0);

    // ---- stream P: weight-only bias kernels ----
    cudaStreamWaitEvent(sP, evWc, 0);
    rowdot_hl<<<2048, 256, 0, sP>>>(bWqT, bWqT + hW, a, alpha);
    rowdot_hl<<<512, 256, 0, sP>>>(bWqT, bWqT + hW, bk, gamma);
    rowdot_hl<<<512, 256, 0, sP>>>(bWkT, bWkT + hW, bq, u);
    rowdot_wo<<<512, 256, 0, sP>>>(Wo, bv, beta);
    rowdot_wo<<<2048, 256, 0, sP>>>(Wo, w, delta);
    dots_kernel<<<5, 256, 0, sP>>>(bq, a, bk, s1, s2);
    // ---- stream P: G-dependent tail ----
    cudaStreamWaitEvent(sP, evG, 0);
    colmv_part<<<dim3(32, 8), Ev, 0, sP>>>(bG, bG + hG, u, pp);
    colmv_final<<<64, 256, 0, sP>>>(pp, p);
    rowdot_kernel<<<2048, 256, 0, sP>>>(Wv, p, sigma, 1);
    tau_kernel<<<64, 256, 0, sP>>>(sigma, s1, s2, bv, w, r);
    cvec_kernel<<<256, 256, 0, sP>>>(r, Wo, bo, c);
    cudaEventRecord(evC, sP);

    // ---- main stream: X (1-term), NT (1-term), epilogue, out (1-term) ----
    cudaStreamWaitEvent(0, evV, 0);
    tgemm<2><<<dim3(4, 4, Bv * Hv), 128, SMEM_DYN>>>(
        bV, bV + hV, bG, bG + hG, bX, bX + hX,
        Ev, Ev, Ev, HEv, Hv, EE, 0, 0, EE, (long)Ev, EHE, 0, 1, 0, 1);
    cudaStreamWaitEvent(0, evWU, 0);
    tgemm<0><<<dim3(4, 4, Bv * 8), 128, SMEM_DYN>>>(
        bX, bX + hX, bU, bU + hU, Tp, nullptr,
        HEv, HEv, HEv, Ev, 1, 0, EHE, 0, 0, 0, EE, 0, 8, PART, 1);
    cudaStreamWaitEvent(0, evC, 0);
    nt_epilogue<<<1024, 256>>>(Tp, PART, 8, alpha, gamma, beta, delta, bNT, bNT + hNT);
    tgemm<1><<<dim3(4, 16, Bv), 128, SMEM_DYN>>>(
        bq16, bq16 + hq, bNT, bNT + hNT, out, c,
        Ev, Ev, Ev, Ev, 1, 0, SE, 0, EE, 0, SE, (long)Ev, 1, 0, 1);
}

// round 16
// speedup vs baseline: 1.0387x; 1.0387x over previous
#include <cuda_runtime.h>
#include <cuda_fp16.h>
#include <cstdint>

#define Bv 4
#define Sv 2048
#define Ev 512
#define Hv 8
#define HEv 4096
#define EEv 262144

// fp32 scratch
__device__ float g_T[(long)Bv * Hv * EEv];
__device__ float g_ksum[Bv * Ev], g_vsum[Bv * Ev];
__device__ float g_cspart[2 * Bv * 16 * Ev];
__device__ float g_pp[32 * 8 * Ev];
__device__ float g_a[Bv * Hv * Ev], g_w[Bv * Hv * Ev];
__device__ float g_alpha[Bv * Hv * Ev], g_gamma[Hv * Ev];
__device__ float g_beta[Hv * Ev], g_delta[Bv * Hv * Ev];
__device__ float g_u[Hv * Ev], g_sigma[Bv * Hv * Ev];
__device__ float g_s1[Bv * Hv], g_s2[Hv];
__device__ float g_c[Bv * Ev];

// fp16 hi|lo buffers (lo at +half)
__device__ __half c_kT [2L * Bv * Ev * Sv];
__device__ __half c_vT [2L * Bv * Ev * Sv];
__device__ __half c_WqT[2L * Hv * EEv];
__device__ __half c_WkT[2L * Hv * EEv];
__device__ __half c_WvT[2L * Hv * EEv];
__device__ __half c_Wo [2L * Ev * HEv];
__device__ __half c_G  [2L * Bv * EEv];
__device__ __half c_U  [2L * Ev * HEv];
__device__ __half c_V  [2L * Hv * EEv];
__device__ __half c_X  [2L * Bv * Ev * HEv];
__device__ __half c_q  [2L * Bv * Sv * Ev];
__device__ __half c_NT [2L * Bv * EEv];

__device__ __forceinline__ uint32_t smem_u32(const void* p) {
    uint32_t a;
    asm("{ .reg .u64 t; cvta.to.shared.u64 t, %1; cvt.u32.u64 %0, t; }" : "=r"(a) : "l"(p));
    return a;
}
__device__ __forceinline__ void cpa16(uint32_t dst, const void* src) {
    asm volatile("cp.async.cg.shared.global [%0], [%1], 16;" :: "r"(dst), "l"(src));
}
__device__ __forceinline__ void ldsm4(uint32_t* r, uint32_t addr) {
    asm volatile("ldmatrix.sync.aligned.m8n8.x4.shared.b16 {%0,%1,%2,%3}, [%4];"
        : "=r"(r[0]), "=r"(r[1]), "=r"(r[2]), "=r"(r[3]) : "r"(addr));
}
__device__ __forceinline__ void mma_f16(float* d, const uint32_t* a, const uint32_t* b) {
    asm volatile("mma.sync.aligned.m16n8k16.row.col.f32.f16.f16.f32 "
        "{%0,%1,%2,%3}, {%4,%5,%6,%7}, {%8,%9}, {%0,%1,%2,%3};"
        : "+f"(d[0]), "+f"(d[1]), "+f"(d[2]), "+f"(d[3])
        : "r"(a[0]), "r"(a[1]), "r"(a[2]), "r"(a[3]), "r"(b[0]), "r"(b[1]));
}
__device__ __forceinline__ __half2 hl2(float x, float y) {
    __half2 r; r.x = __float2half(x); r.y = __float2half(y); return r;
}
__device__ __forceinline__ float wredu(float s) {
    #pragma unroll
    for (int off = 16; off > 0; off >>= 1) s += __shfl_xor_sync(0xFFFFFFFFu, s, off);
    return s;
}

#define STAGE 32768
#define SMEM_DYN (3 * STAGE)

// MODE: 0 = fp32 (split-K partials), 1 = fp32 + bias, 2 = fp16 hi/lo (aux = lo base)
template <int MODE>
__global__ void __launch_bounds__(128, 2)
tgemm(const __half* __restrict__ Ahi, const __half* __restrict__ Alo,
      const __half* __restrict__ Bhi, const __half* __restrict__ Blo,
      void* __restrict__ Cout, const void* __restrict__ aux,
      int K, int lda, int ldb, int ldc, int zmod,
      long aS1, long aS2, long bS1, long bS2, long cS1, long cS2,
      long auxStride, int nsplit, long partStride, int nterms)
{
    extern __shared__ __align__(128) char dsm[];
    uint32_t sbase = smem_u32(dsm);

    int tid = threadIdx.x, wid = tid >> 5, lane = tid & 31;
    int zPer = gridDim.z / nsplit;
    int split = blockIdx.z / zPer;
    int z = blockIdx.z % zPer;
    int zm = z % zmod, zd = z / zmod;
    Ahi += zm * aS1 + zd * aS2;  Alo += zm * aS1 + zd * aS2;
    Bhi += zm * bS1 + zd * bS2;  Blo += zm * bS1 + zd * bS2;
    int m0 = blockIdx.y * 128, n0 = blockIdx.x * 128;

    const int Ks = K / nsplit;
    const int CPP = Ks >> 6;
    const int NC = nterms * CPP;
    const int kofs = split * Ks;

    int srow = tid >> 3, scs = tid & 7;

    auto issue = [&](int c) {
        int phase = c / CPP;
        int kpos = kofs + ((c - phase * CPP) << 6);
        const __half* pa = (nterms >= 2 && phase == nterms - 1) ? Alo : Ahi;
        const __half* pb = (phase == 1 && nterms == 3) ? Blo : Bhi;
        uint32_t sb = sbase + (uint32_t)((c % 3) * STAGE);
        #pragma unroll
        for (int t = 0; t < 16; t++) {
            int isB = t >> 3;
            int row = srow + ((t & 7) << 4);
            const __half* src = isB
                ? pb + (long)(n0 + row) * ldb + kpos + (scs << 3)
                : pa + (long)(m0 + row) * lda + kpos + (scs << 3);
            uint32_t bo = (uint32_t)((row << 7) + (scs << 4));
            bo ^= (uint32_t)((row & 7) << 4);
            cpa16(sb + (uint32_t)(isB << 14) + bo, src);
        }
        asm volatile("cp.async.commit_group;" ::: "memory");
    };

    issue(0);
    issue(1);

    float acc[4][8][4] = {};
    int moff = (wid & 1) << 6;
    int noff = (wid >> 1) << 6;

    for (int c = 0; c < NC; c++) {
        if (c + 1 < NC) asm volatile("cp.async.wait_group 1;" ::: "memory");
        else            asm volatile("cp.async.wait_group 0;" ::: "memory");
        __syncthreads();
        if (c + 2 < NC) issue(c + 2);
        uint32_t sb = sbase + (uint32_t)((c % 3) * STAGE);

        #pragma unroll
        for (int ks = 0; ks < 4; ks++) {
            uint32_t afr[4][4];
            #pragma unroll
            for (int i = 0; i < 4; i++) {
                int row = moff + (i << 4) + (lane & 15);
                int colb = (ks << 5) + ((lane >> 4) << 4);
                uint32_t bo = (uint32_t)((row << 7) + colb) ^ (uint32_t)((row & 7) << 4);
                ldsm4(afr[i], sb + bo);
            }
            uint32_t bfr[8][2];
            #pragma unroll
            for (int j2 = 0; j2 < 4; j2++) {
                int row = noff + (j2 << 4) + ((lane >> 4) << 3) + (lane & 7);
                int colb = (ks << 5) + (((lane >> 3) & 1) << 4);
                uint32_t bo = (uint32_t)((row << 7) + colb) ^ (uint32_t)((row & 7) << 4);
                uint32_t r[4];
                ldsm4(r, sb + 16384u + bo);
                bfr[2 * j2][0] = r[0]; bfr[2 * j2][1] = r[1];
                bfr[2 * j2 + 1][0] = r[2]; bfr[2 * j2 + 1][1] = r[3];
            }
            #pragma unroll
            for (int i = 0; i < 4; i++)
                #pragma unroll
                for (int j = 0; j < 8; j++)
                    mma_f16(acc[i][j], afr[i], bfr[j]);
        }
    }

    int g = lane >> 2, t4 = lane & 3;
    if (MODE == 2) {
        __half* hi = (__half*)Cout + zm * cS1 + zd * cS2;
        __half* lo = (__half*)aux  + zm * cS1 + zd * cS2;
        #pragma unroll
        for (int i = 0; i < 4; i++) {
            int row0 = m0 + moff + (i << 4) + g;
            #pragma unroll
            for (int j = 0; j < 8; j++) {
                int col = n0 + noff + (j << 3) + (t4 << 1);
                #pragma unroll
                for (int rr = 0; rr < 2; rr++) {
                    long off = (long)(row0 + 8 * rr) * ldc + col;
                    float vx = acc[i][j][2 * rr], vy = acc[i][j][2 * rr + 1];
                    __half2 h = hl2(vx, vy);
                    __half2 l = hl2(vx - __half2float(h.x), vy - __half2float(h.y));
                    *reinterpret_cast<__half2*>(hi + off) = h;
                    *reinterpret_cast<__half2*>(lo + off) = l;
                }
            }
        }
    } else {
        float* C = (float*)Cout + zm * cS1 + zd * cS2 + (long)split * partStride;
        const float* bp = (MODE == 1) ? ((const float*)aux + zd * auxStride) : nullptr;
        #pragma unroll
        for (int i = 0; i < 4; i++) {
            int row0 = m0 + moff + (i << 4) + g;
            #pragma unroll
            for (int j = 0; j < 8; j++) {
                int col = n0 + noff + (j << 3) + (t4 << 1);
                float bx = 0.f, by = 0.f;
                if (MODE == 1) { float2 bb = *reinterpret_cast<const float2*>(bp + col); bx = bb.x; by = bb.y; }
                float2 o0 = make_float2(acc[i][j][0] + bx, acc[i][j][1] + by);
                float2 o1 = make_float2(acc[i][j][2] + bx, acc[i][j][3] + by);
                *reinterpret_cast<float2*>(&C[(long)row0 * ldc + col]) = o0;
                *reinterpret_cast<float2*>(&C[(long)(row0 + 8) * ldc + col]) = o1;
            }
        }
    }
}

__global__ void reduce_hl(const float* __restrict__ parts, long pstride, int nsplit,
                          __half* __restrict__ hi, __half* __restrict__ lo) {
    long i = ((long)blockIdx.x * blockDim.x + threadIdx.x) * 4;
    float4 s = *reinterpret_cast<const float4*>(parts + i);
    for (int p = 1; p < nsplit; p++) {
        float4 t = *reinterpret_cast<const float4*>(parts + p * pstride + i);
        s.x += t.x; s.y += t.y; s.z += t.z; s.w += t.w;
    }
    __half2 h0 = hl2(s.x, s.y), h1 = hl2(s.z, s.w);
    __half2 l0 = hl2(s.x - __half2float(h0.x), s.y - __half2float(h0.y));
    __half2 l1 = hl2(s.z - __half2float(h1.x), s.w - __half2float(h1.y));
    *reinterpret_cast<__half2*>(hi + i) = h0;
    *reinterpret_cast<__half2*>(hi + i + 2) = h1;
    *reinterpret_cast<__half2*>(lo + i) = l0;
    *reinterpret_cast<__half2*>(lo + i + 2) = l1;
}

__global__ void nt_epilogue(const float* __restrict__ parts, long pstride, int nsplit,
                            const float* __restrict__ alpha, const float* __restrict__ gamma,
                            const float* __restrict__ beta, const float* __restrict__ delta,
                            __half* __restrict__ hi, __half* __restrict__ lo) {
    long i = ((long)blockIdx.x * blockDim.x + threadIdx.x) * 4;
    int e = (int)(i & 511);
    int o3 = (int)((i >> 9) & 511);
    int b = (int)(i >> 18);
    float4 s = *reinterpret_cast<const float4*>(parts + i);
    for (int p = 1; p < nsplit; p++) {
        float4 t = *reinterpret_cast<const float4*>(parts + p * pstride + i);
        s.x += t.x; s.y += t.y; s.z += t.z; s.w += t.w;
    }
    #pragma unroll
    for (int h = 0; h < Hv; h++) {
        float be = beta[h * Ev + o3];
        float de = delta[(b * Hv + h) * Ev + o3];
        float4 al = *reinterpret_cast<const float4*>(alpha + (long)(b * Hv + h) * Ev + e);
        float4 ga = *reinterpret_cast<const float4*>(gamma + h * Ev + e);
        s.x += be * (al.x + (float)Sv * ga.x) + de * ga.x;
        s.y += be * (al.y + (float)Sv * ga.y) + de * ga.y;
        s.z += be * (al.z + (float)Sv * ga.z) + de * ga.z;
        s.w += be * (al.w + (float)Sv * ga.w) + de * ga.w;
    }
    const float invE = 1.0f / (float)Ev;
    s.x *= invE; s.y *= invE; s.z *= invE; s.w *= invE;
    __half2 h0 = hl2(s.x, s.y), h1 = hl2(s.z, s.w);
    __half2 l0 = hl2(s.x - __half2float(h0.x), s.y - __half2float(h0.y));
    __half2 l1 = hl2(s.z - __half2float(h1.x), s.w - __half2float(h1.y));
    *reinterpret_cast<__half2*>(hi + i) = h0;
    *reinterpret_cast<__half2*>(hi + i + 2) = h1;
    *reinterpret_cast<__half2*>(lo + i) = l0;
    *reinterpret_cast<__half2*>(lo + i + 2) = l1;
}

__global__ void conv_split(const float* __restrict__ src, __half* __restrict__ hi,
                           __half* __restrict__ lo) {
    long i = ((long)blockIdx.x * blockDim.x + threadIdx.x) * 4;
    float4 x = *reinterpret_cast<const float4*>(src + i);
    __half2 h0 = hl2(x.x, x.y), h1 = hl2(x.z, x.w);
    __half2 l0 = hl2(x.x - __half2float(h0.x), x.y - __half2float(h0.y));
    __half2 l1 = hl2(x.z - __half2float(h1.x), x.w - __half2float(h1.y));
    *reinterpret_cast<__half2*>(hi + i) = h0;
    *reinterpret_cast<__half2*>(hi + i + 2) = h1;
    *reinterpret_cast<__half2*>(lo + i) = l0;
    *reinterpret_cast<__half2*>(lo + i + 2) = l1;
}

__global__ void conv_hi(const float* __restrict__ src, __half* __restrict__ hi) {
    long i = ((long)blockIdx.x * blockDim.x + threadIdx.x) * 4;
    float4 x = *reinterpret_cast<const float4*>(src + i);
    *reinterpret_cast<__half2*>(hi + i) = hl2(x.x, x.y);
    *reinterpret_cast<__half2*>(hi + i + 2) = hl2(x.z, x.w);
}

__global__ void conv_tsplit(const float* __restrict__ src, __half* __restrict__ hi,
                            __half* __restrict__ lo,
                            int srcLd, long srcZ, int dstLd, long dstZ, int wlo) {
    __shared__ float tile[32][33];
    int zz = blockIdx.z;
    src += (long)zz * srcZ;
    long dz = (long)zz * dstZ;
    int k0 = blockIdx.x * 32, r0 = blockIdx.y * 32;
    int tx = threadIdx.x, ty = threadIdx.y;
    #pragma unroll
    for (int i = 0; i < 4; i++)
        tile[ty + 8 * i][tx] = src[(long)(k0 + ty + 8 * i) * srcLd + r0 + tx];
    __syncthreads();
    #pragma unroll
    for (int i = 0; i < 4; i++) {
        int r = r0 + ty + 8 * i, kk = k0 + tx;
        float x = tile[tx][ty + 8 * i];
        __half h = __float2half(x);
        hi[dz + (long)r * dstLd + kk] = h;
        if (wlo) lo[dz + (long)r * dstLd + kk] = __float2half(x - __half2float(h));
    }
}

// merged Wq + Wk transpose-split: grid (16, 16, 16); z: h = zz&7, which = zz>>3
__global__ void conv_t2(const float* __restrict__ Wq, const float* __restrict__ Wk,
                        __half* __restrict__ qhi, __half* __restrict__ qlo,
                        __half* __restrict__ khi, __half* __restrict__ klo) {
    __shared__ float tile[32][33];
    int zz = blockIdx.z;
    int h = zz & 7, which = zz >> 3;
    const float* src = (which ? Wk : Wq) + (long)h * EEv;
    __half* hi = (which ? khi : qhi) + (long)h * EEv;
    __half* lo = (which ? klo : qlo) + (long)h * EEv;
    int k0 = blockIdx.x * 32, r0 = blockIdx.y * 32;
    int tx = threadIdx.x, ty = threadIdx.y;
    #pragma unroll
    for (int i = 0; i < 4; i++)
        tile[ty + 8 * i][tx] = src[(long)(k0 + ty + 8 * i) * Ev + r0 + tx];
    __syncthreads();
    #pragma unroll
    for (int i = 0; i < 4; i++) {
        int r = r0 + ty + 8 * i, kk = k0 + tx;
        float x = tile[tx][ty + 8 * i];
        __half hh = __float2half(x);
        hi[(long)r * Ev + kk] = hh;
        lo[(long)r * Ev + kk] = __float2half(x - __half2float(hh));
    }
}

// merged k+v transpose (hi only): grid (64, 16, 8)
__global__ void conv_tkv(const float* __restrict__ k, const float* __restrict__ v,
                         __half* __restrict__ kT, __half* __restrict__ vT) {
    __shared__ float tile[32][33];
    int zz = blockIdx.z;
    int b = zz & 3, which = zz >> 2;
    const float* src = (which ? v : k) + (long)b * Sv * Ev;
    __half* dst = (which ? vT : kT) + (long)b * Ev * Sv;
    int k0 = blockIdx.x * 32, r0 = blockIdx.y * 32;
    int tx = threadIdx.x, ty = threadIdx.y;
    #pragma unroll
    for (int i = 0; i < 4; i++)
        tile[ty + 8 * i][tx] = src[(long)(k0 + ty + 8 * i) * Ev + r0 + tx];
    __syncthreads();
    #pragma unroll
    for (int i = 0; i < 4; i++)
        dst[(long)(r0 + ty + 8 * i) * Sv + k0 + tx] = __float2half(tile[tx][ty + 8 * i]);
}

// stage-1 column sums: grid (16, Bv, 2), block 512
__global__ void csum_part(const float* __restrict__ k, const float* __restrict__ v,
                          float* __restrict__ part) {
    int chunk = blockIdx.x, b = blockIdx.y, which = blockIdx.z, e = threadIdx.x;
    const float* src = (which ? v : k) + (long)b * Sv * Ev + (long)chunk * 128 * Ev + e;
    float s = 0.f;
    for (int i = 0; i < 128; i++) s += src[(long)i * Ev];
    part[(((long)which * Bv + b) * 16 + chunk) * Ev + e] = s;
}

// fused csum_final + rowdot for a and w. grid 4096, block 256 (8 warps = 8 outputs).
// blocks [0,2048): a (W=Wk, which=0); [2048,4096): w (W=Wv, which=1).
// Also writes ksum/vsum (once, by the 64-block group's first block) for later use? not needed.
__global__ void rowdot_aw(const float* __restrict__ Wk, const float* __restrict__ Wv,
                          const float* __restrict__ cspart,
                          float* __restrict__ a, float* __restrict__ w) {
    __shared__ float xs[Ev];
    int j = blockIdx.x;
    int which = (j >= 2048) ? 1 : 0;
    int jj = j - which * 2048;
    int zz = jj >> 6;                 // 0..31
    int obase = (jj & 63) * 8;
    int b = zz >> 3, h = zz & 7;
    int tid = threadIdx.x;
    // reduce 16 partials of colsum into xs
    const float* cp = cspart + (((long)which * Bv + b) * 16) * Ev;
    #pragma unroll
    for (int t = 0; t < 2; t++) {
        int idx = tid + t * 256;
        float s = 0.f;
        #pragma unroll
        for (int i = 0; i < 16; i++) s += cp[(long)i * Ev + idx];
        xs[idx] = s;
    }
    __syncthreads();
    int wid = tid >> 5, lane = tid & 31;
    int o = obase + wid;
    const float* W = which ? Wv : Wk;
    const float* wr = W + (long)(h * Ev + o) * Ev;
    float s = 0.f;
    for (int e = lane; e < Ev; e += 32) s += wr[e] * xs[e];
    s = wredu(s);
    if (lane == 0) (which ? w : a)[(long)zz * Ev + o] = s;
}

// fused bias kernel: alpha | gamma | u | beta | delta | dots. 5637 blocks x 256.
__global__ void bias_pack(const __half* __restrict__ WqThi, const __half* __restrict__ WqTlo,
                          const __half* __restrict__ WkThi, const __half* __restrict__ WkTlo,
                          const float* __restrict__ Wo,
                          const float* __restrict__ a, const float* __restrict__ w,
                          const float* __restrict__ bq, const float* __restrict__ bk,
                          const float* __restrict__ bv,
                          float* __restrict__ alpha, float* __restrict__ gamma,
                          float* __restrict__ u, float* __restrict__ beta,
                          float* __restrict__ delta, float* __restrict__ s1,
                          float* __restrict__ s2) {
    int gw = (blockIdx.x * blockDim.x + threadIdx.x) >> 5, lane = threadIdx.x & 31;
    float s = 0.f;
    if (gw < 16384) {                         // alpha[zz*E+e]
        int e = gw & 511, zz = gw >> 9, h = zz & 7;
        long wofs = (long)h * EEv + (long)e * Ev;
        const float* xr = a + (long)zz * Ev;
        for (int o = lane; o < Ev; o += 32)
            s += (__half2float(WqThi[wofs + o]) + __half2float(WqTlo[wofs + o])) * xr[o];
        s = wredu(s);
        if (lane == 0) alpha[gw] = s;
    } else if (gw < 20480) {                  // gamma[h*E+e]
        int g2 = gw - 16384, e = g2 & 511, h = g2 >> 9;
        long wofs = (long)h * EEv + (long)e * Ev;
        const float* xr = bk + (long)h * Ev;
        for (int o = lane; o < Ev; o += 32)
            s += (__half2float(WqThi[wofs + o]) + __half2float(WqTlo[wofs + o])) * xr[o];
        s = wredu(s);
        if (lane == 0) gamma[g2] = s;
    } else if (gw < 24576) {                  // u[h*E+e1]
        int g2 = gw - 20480, e = g2 & 511, h = g2 >> 9;
        long wofs = (long)h * EEv + (long)e * Ev;
        const float* xr = bq + (long)h * Ev;
        for (int o = lane; o < Ev; o += 32)
            s += (__half2float(WkThi[wofs + o]) + __half2float(WkTlo[wofs + o])) * xr[o];
        s = wredu(s);
        if (lane == 0) u[g2] = s;
    } else if (gw < 28672) {                  // beta[h*E+o3]
        int g2 = gw - 24576, o3 = g2 & 511, h = g2 >> 9;
        const float* wr = Wo + (long)o3 * HEv + (long)h * Ev;
        const float* xr = bv + (long)h * Ev;
        for (int e = lane; e < Ev; e += 32) s += wr[e] * xr[e];
        s = wredu(s);
        if (lane == 0) beta[(long)h * Ev + o3] = s;
    } else if (gw < 45056) {                  // delta[zz*E+o3]
        int g2 = gw - 28672, o3 = g2 & 511, zz = g2 >> 9, h = zz & 7;
        const float* wr = Wo + (long)o3 * HEv + (long)h * Ev;
        const float* xr = w + (long)zz * Ev;
        for (int e = lane; e < Ev; e += 32) s += wr[e] * xr[e];
        s = wredu(s);
        if (lane == 0) delta[(long)zz * Ev + o3] = s;
    } else if (gw < 45096) {                  // dots
        int idx = gw - 45056;
        const float* xa;
        const float* xb;
        if (idx < 32) { xa = bq + (idx & 7) * Ev; xb = a + (long)idx * Ev; }
        else          { xa = bq + (idx - 32) * Ev; xb = bk + (idx - 32) * Ev; }
        for (int o = lane; o < Ev; o += 32) s += xa[o] * xb[o];
        s = wredu(s);
        if (lane == 0) { if (idx < 32) s1[idx] = s; else s2[idx - 32] = s; }
    }
}

// stage-1 colmv: grid (32, 8), block 512
__global__ void colmv_part(const __half* __restrict__ Ghi, const __half* __restrict__ Glo,
                           const float* __restrict__ u, float* __restrict__ pp) {
    int zz = blockIdx.x, chunk = blockIdx.y, tid = threadIdx.x;
    int b = zz >> 3, h = zz & (Hv - 1);
    __shared__ float us[64];
    if (tid < 64) us[tid] = u[h * Ev + chunk * 64 + tid];
    __syncthreads();
    const __half* gh = Ghi + (long)b * EEv + (long)chunk * 64 * Ev;
    const __half* gl = Glo + (long)b * EEv + (long)chunk * 64 * Ev;
    float acc = 0.f;
    #pragma unroll 4
    for (int i = 0; i < 64; i++) {
        long idx = (long)i * Ev + tid;
        acc += us[i] * (__half2float(gh[idx]) + __half2float(gl[idx]));
    }
    pp[((long)zz * 8 + chunk) * Ev + tid] = acc;
}

// fused colmv_final + sigma. grid 2048, block 256 (8 outputs/block).
__global__ void sigma_f(const float* __restrict__ pp, const float* __restrict__ Wv,
                        float* __restrict__ sigma) {
    __shared__ float ps[Ev];
    int j = blockIdx.x;
    int zz = j >> 6;
    int obase = (j & 63) * 8;
    int h = zz & 7;
    int tid = threadIdx.x;
    const float* q = pp + (long)zz * 8 * Ev;
    #pragma unroll
    for (int t = 0; t < 2; t++) {
        int idx = tid + t * 256;
        float s = 0.f;
        #pragma unroll
        for (int i = 0; i < 8; i++) s += q[(long)i * Ev + idx];
        ps[idx] = s;
    }
    __syncthreads();
    int wid = tid >> 5, lane = tid & 31;
    int o = obase + wid;
    const float* wr = Wv + (long)(h * Ev + o) * Ev;
    float s = 0.f;
    for (int o2 = lane; o2 < Ev; o2 += 32) s += wr[o2] * ps[o2];
    s = wredu(s);
    if (lane == 0) sigma[(long)zz * Ev + o] = s;
}

// fused tau + cvec: c[b*E+o3] = bo + (1/E) sum_f Wo[o3][f]*tau(b,f). 256 blocks x 256.
__global__ void cvec_f(const float* __restrict__ sigma, const float* __restrict__ s1,
                       const float* __restrict__ s2, const float* __restrict__ bv,
                       const float* __restrict__ w, const float* __restrict__ Wo,
                       const float* __restrict__ bo, float* __restrict__ c) {
    int gw = (blockIdx.x * blockDim.x + threadIdx.x) >> 5, lane = threadIdx.x & 31;
    int o3 = gw & (Ev - 1), b = gw >> 9;
    const float* wr = Wo + (long)o3 * HEv;
    float s = 0.f;
    for (int f = lane; f < HEv; f += 32) {
        int h = f >> 9, o2 = f & 511;
        int zz = b * Hv + h;
        float bvv = bv[h * Ev + o2];
        float tau = sigma[(long)zz * Ev + o2] + s1[zz] * bvv
                  + s2[h] * (w[(long)zz * Ev + o2] + (float)Sv * bvv);
        s += wr[f] * tau;
    }
    s = wredu(s);
    if (lane == 0) c[gw] = s * (1.0f / (float)Ev) + bo[o3];
}

extern "C" void kernel_launch(void* const* d_in, const int* in_sizes, int n_in,
                              void* d_out, int out_size) {
    const float* q  = (const float*)d_in[0];
    const float* k  = (const float*)d_in[1];
    const float* v  = (const float*)d_in[2];
    const float* Wq = (const float*)d_in[3];
    const float* bq = (const float*)d_in[4];
    const float* Wk = (const float*)d_in[5];
    const float* bk = (const float*)d_in[6];
    const float* Wv = (const float*)d_in[7];
    const float* bv = (const float*)d_in[8];
    const float* Wo = (const float*)d_in[9];
    const float* bo = (const float*)d_in[10];
    float* out = (float*)d_out;

    float *Tp, *cspart, *pp, *a, *w, *alpha, *gamma, *beta, *delta, *u, *sigma, *s1, *s2, *c;
    cudaGetSymbolAddress((void**)&Tp, g_T);
    cudaGetSymbolAddress((void**)&cspart, g_cspart);
    cudaGetSymbolAddress((void**)&pp, g_pp);
    cudaGetSymbolAddress((void**)&a, g_a);
    cudaGetSymbolAddress((void**)&w, g_w);
    cudaGetSymbolAddress((void**)&alpha, g_alpha);
    cudaGetSymbolAddress((void**)&gamma, g_gamma);
    cudaGetSymbolAddress((void**)&beta, g_beta);
    cudaGetSymbolAddress((void**)&delta, g_delta);
    cudaGetSymbolAddress((void**)&u, g_u);
    cudaGetSymbolAddress((void**)&sigma, g_sigma);
    cudaGetSymbolAddress((void**)&s1, g_s1);
    cudaGetSymbolAddress((void**)&s2, g_s2);
    cudaGetSymbolAddress((void**)&c, g_c);

    __half *kT, *vT, *bWqT, *bWkT, *bWvT, *bWo, *bG, *bU, *bV, *bX, *bq16, *bNT;
    cudaGetSymbolAddress((void**)&kT, c_kT);
    cudaGetSymbolAddress((void**)&vT, c_vT);
    cudaGetSymbolAddress((void**)&bWqT, c_WqT);
    cudaGetSymbolAddress((void**)&bWkT, c_WkT);
    cudaGetSymbolAddress((void**)&bWvT, c_WvT);
    cudaGetSymbolAddress((void**)&bWo, c_Wo);
    cudaGetSymbolAddress((void**)&bG, c_G);
    cudaGetSymbolAddress((void**)&bU, c_U);
    cudaGetSymbolAddress((void**)&bV, c_V);
    cudaGetSymbolAddress((void**)&bX, c_X);
    cudaGetSymbolAddress((void**)&bq16, c_q);
    cudaGetSymbolAddress((void**)&bNT, c_NT);

    static cudaStream_t sW = nullptr, sP = nullptr;
    static cudaEvent_t evRoot, evWc, evV, evWU, evG, evB, evC;
    if (!sW) {
        cudaStreamCreateWithFlags(&sW, cudaStreamNonBlocking);
        cudaStreamCreateWithFlags(&sP, cudaStreamNonBlocking);
        cudaEventCreateWithFlags(&evRoot, cudaEventDisableTiming);
        cudaEventCreateWithFlags(&evWc, cudaEventDisableTiming);
        cudaEventCreateWithFlags(&evV, cudaEventDisableTiming);
        cudaEventCreateWithFlags(&evWU, cudaEventDisableTiming);
        cudaEventCreateWithFlags(&evG, cudaEventDisableTiming);
        cudaEventCreateWithFlags(&evB, cudaEventDisableTiming);
        cudaEventCreateWithFlags(&evC, cudaEventDisableTiming);
        cudaFuncSetAttribute(tgemm<0>, cudaFuncAttributeMaxDynamicSharedMemorySize, SMEM_DYN);
        cudaFuncSetAttribute(tgemm<1>, cudaFuncAttributeMaxDynamicSharedMemorySize, SMEM_DYN);
        cudaFuncSetAttribute(tgemm<2>, cudaFuncAttributeMaxDynamicSharedMemorySize, SMEM_DYN);
    }

    const long ES = (long)Ev * Sv, EE = EEv, SE = (long)Sv * Ev, EHE = (long)Ev * HEv;
    const long hKT = (long)Bv * ES, hW = (long)Hv * EEv, hWo = (long)Ev * HEv;
    const long hG = (long)Bv * EEv, hU = (long)Ev * HEv, hV = (long)Hv * EEv;
    const long hX = (long)Bv * Ev * HEv, hq = (long)Bv * SE, hNT = (long)Bv * EEv;
    const long PART = (long)Bv * EEv;

    dim3 tb(32, 8);

    cudaEventRecord(evRoot, 0);

    // ---- stream W: V first (2-term), then U (2-term) ----
    cudaStreamWaitEvent(sW, evRoot, 0);
    conv_tsplit<<<dim3(16, 16, Hv), tb, 0, sW>>>(Wv, bWvT, bWvT + hW, Ev, EE, Ev, EE, 1);
    conv_split<<<2048, 256, 0, sW>>>(Wo, bWo, bWo + hWo);
    tgemm<2><<<dim3(4, 4, Hv), 128, SMEM_DYN, sW>>>(
        bWo, bWo + hWo, bWvT, bWvT + hW, bV, bV + hV,
        Ev, HEv, Ev, Ev, Hv, (long)Ev, 0, EE, 0, EE, 0, 0, 1, 0, 2);
    cudaEventRecord(evV, sW);
    conv_t2<<<dim3(16, 16, 16), tb, 0, sW>>>(Wq, Wk, bWqT, bWqT + hW, bWkT, bWkT + hW);
    cudaEventRecord(evWc, sW);
    tgemm<2><<<dim3(4, 4, Hv), 128, SMEM_DYN, sW>>>(
        bWqT, bWqT + hW, bWkT, bWkT + hW, bU, bU + hU,
        Ev, Ev, Ev, HEv, Hv, EE, 0, EE, 0, (long)Ev, 0, 0, 1, 0, 2);
    cudaEventRecord(evWU, sW);

    // ---- stream P: colsum partials, fused a/w, q conv ----
    cudaStreamWaitEvent(sP, evRoot, 0);
    csum_part<<<dim3(16, Bv, 2), Ev, 0, sP>>>(k, v, cspart);
    rowdot_aw<<<4096, 256, 0, sP>>>(Wk, Wv, cspart, a, w);
    conv_hi<<<4096, 256, 0, sP>>>(q, bq16);

    // ---- main stream: merged k/v transpose, G (1-term, split-8) ----
    conv_tkv<<<dim3(64, 16, Bv * 2), tb>>>(k, v, kT, vT);
    tgemm<0><<<dim3(4, 4, Bv * 8), 128, SMEM_DYN>>>(
        kT, kT + hKT, vT, vT + hKT, Tp, nullptr,
        Sv, Sv, Sv, Ev, 1, 0, ES, 0, ES, 0, EE, 0, 8, PART, 1);
    reduce_hl<<<1024, 256>>>(Tp, PART, 8, bG, bG + hG);
    cudaEventRecord(evG, 0);

    // ---- stream P: fused bias kernel, then G-dependent tail ----
    cudaStreamWaitEvent(sP, evWc, 0);
    bias_pack<<<5637, 256, 0, sP>>>(bWqT, bWqT + hW, bWkT, bWkT + hW, Wo,
                                    a, w, bq, bk, bv,
                                    alpha, gamma, u, beta, delta, s1, s2);
    cudaEventRecord(evB, sP);
    cudaStreamWaitEvent(sP, evG, 0);
    colmv_part<<<dim3(32, 8), Ev, 0, sP>>>(bG, bG + hG, u, pp);
    sigma_f<<<2048, 256, 0, sP>>>(pp, Wv, sigma);
    cvec_f<<<256, 256, 0, sP>>>(sigma, s1, s2, bv, w, Wo, bo, c);
    cudaEventRecord(evC, sP);

    // ---- main stream: X (1-term), NT (1-term), epilogue, out (1-term) ----
    cudaStreamWaitEvent(0, evV, 0);
    tgemm<2><<<dim3(4, 4, Bv * Hv), 128, SMEM_DYN>>>(
        bV, bV + hV, bG, bG + hG, bX, bX + hX,
        Ev, Ev, Ev, HEv, Hv, EE, 0, 0, EE, (long)Ev, EHE, 0, 1, 0, 1);
    cudaStreamWaitEvent(0, evWU, 0);
    tgemm<0><<<dim3(4, 4, Bv * 8), 128, SMEM_DYN>>>(
        bX, bX + hX, bU, bU + hU, Tp, nullptr,
        HEv, HEv, HEv, Ev, 1, 0, EHE, 0, 0, 0, EE, 0, 8, PART, 1);
    cudaStreamWaitEvent(0, evB, 0);
    nt_epilogue<<<1024, 256>>>(Tp, PART, 8, alpha, gamma, beta, delta, bNT, bNT + hNT);
    cudaStreamWaitEvent(0, evC, 0);
    tgemm<1><<<dim3(4, 16, Bv), 128, SMEM_DYN>>>(
        bq16, bq16 + hq, bNT, bNT + hNT, out, c,
        Ev, Ev, Ev, Ev, 1, 0, SE, 0, EE, 0, SE, (long)Ev, 1, 0, 1);
}

// round 17
// speedup vs baseline: 1.1549x; 1.1119x over previous
#include <cuda_runtime.h>
#include <cuda_fp16.h>
#include <cstdint>

#define Bv 4
#define Sv 2048
#define Ev 512
#define Hv 8
#define HEv 4096
#define EEv 262144

// fp32 scratch
__device__ float g_T[(long)Bv * Hv * EEv];
__device__ float g_cspart[2 * Bv * 16 * Ev];
__device__ float g_pp[32 * 8 * Ev];
__device__ float g_a[Bv * Hv * Ev], g_w[Bv * Hv * Ev];
__device__ float g_alpha[Bv * Hv * Ev], g_gamma[Hv * Ev];
__device__ float g_beta[Hv * Ev], g_delta[Bv * Hv * Ev];
__device__ float g_u[Hv * Ev], g_sigma[Bv * Hv * Ev];
__device__ float g_s1[Bv * Hv], g_s2[Hv];
__device__ float g_c[Bv * Ev];

// fp16 hi|lo buffers (lo at +half)
__device__ __half c_kT [2L * Bv * Ev * Sv];
__device__ __half c_vT [2L * Bv * Ev * Sv];
__device__ __half c_WqT[2L * Hv * EEv];
__device__ __half c_WkT[2L * Hv * EEv];
__device__ __half c_WvT[2L * Hv * EEv];
__device__ __half c_Wo [2L * Ev * HEv];
__device__ __half c_G  [2L * Bv * EEv];
__device__ __half c_U  [2L * Ev * HEv];
__device__ __half c_V  [2L * Hv * EEv];
__device__ __half c_X  [2L * Bv * Ev * HEv];
__device__ __half c_q  [2L * Bv * Sv * Ev];
__device__ __half c_NT [2L * Bv * EEv];

__device__ __forceinline__ uint32_t smem_u32(const void* p) {
    uint32_t a;
    asm("{ .reg .u64 t; cvta.to.shared.u64 t, %1; cvt.u32.u64 %0, t; }" : "=r"(a) : "l"(p));
    return a;
}
__device__ __forceinline__ void cpa16(uint32_t dst, const void* src) {
    asm volatile("cp.async.cg.shared.global [%0], [%1], 16;" :: "r"(dst), "l"(src));
}
__device__ __forceinline__ void ldsm4(uint32_t* r, uint32_t addr) {
    asm volatile("ldmatrix.sync.aligned.m8n8.x4.shared.b16 {%0,%1,%2,%3}, [%4];"
        : "=r"(r[0]), "=r"(r[1]), "=r"(r[2]), "=r"(r[3]) : "r"(addr));
}
__device__ __forceinline__ void mma_f16(float* d, const uint32_t* a, const uint32_t* b) {
    asm volatile("mma.sync.aligned.m16n8k16.row.col.f32.f16.f16.f32 "
        "{%0,%1,%2,%3}, {%4,%5,%6,%7}, {%8,%9}, {%0,%1,%2,%3};"
        : "+f"(d[0]), "+f"(d[1]), "+f"(d[2]), "+f"(d[3])
        : "r"(a[0]), "r"(a[1]), "r"(a[2]), "r"(a[3]), "r"(b[0]), "r"(b[1]));
}
__device__ __forceinline__ __half2 hl2(float x, float y) {
    __half2 r; r.x = __float2half(x); r.y = __float2half(y); return r;
}
__device__ __forceinline__ float wredu(float s) {
    #pragma unroll
    for (int off = 16; off > 0; off >>= 1) s += __shfl_xor_sync(0xFFFFFFFFu, s, off);
    return s;
}

#define STAGE 32768
#define SMEM_DYN (3 * STAGE)

// MODE: 0 = fp32 (split-K partials), 1 = fp32 + bias, 2 = fp16 hi/lo (aux = lo base)
template <int MODE>
__global__ void __launch_bounds__(128, 2)
tgemm(const __half* __restrict__ Ahi, const __half* __restrict__ Alo,
      const __half* __restrict__ Bhi, const __half* __restrict__ Blo,
      void* __restrict__ Cout, const void* __restrict__ aux,
      int K, int lda, int ldb, int ldc, int zmod,
      long aS1, long aS2, long bS1, long bS2, long cS1, long cS2,
      long auxStride, int nsplit, long partStride, int nterms)
{
    extern __shared__ __align__(128) char dsm[];
    uint32_t sbase = smem_u32(dsm);

    int tid = threadIdx.x, wid = tid >> 5, lane = tid & 31;
    int zPer = gridDim.z / nsplit;
    int split = blockIdx.z / zPer;
    int z = blockIdx.z % zPer;
    int zm = z % zmod, zd = z / zmod;
    Ahi += zm * aS1 + zd * aS2;  Alo += zm * aS1 + zd * aS2;
    Bhi += zm * bS1 + zd * bS2;  Blo += zm * bS1 + zd * bS2;
    int m0 = blockIdx.y * 128, n0 = blockIdx.x * 128;

    const int Ks = K / nsplit;
    const int CPP = Ks >> 6;
    const int NC = nterms * CPP;
    const int kofs = split * Ks;

    int srow = tid >> 3, scs = tid & 7;

    auto issue = [&](int c) {
        int phase = c / CPP;
        int kpos = kofs + ((c - phase * CPP) << 6);
        const __half* pa = (nterms >= 2 && phase == nterms - 1) ? Alo : Ahi;
        const __half* pb = (phase == 1 && nterms == 3) ? Blo : Bhi;
        uint32_t sb = sbase + (uint32_t)((c % 3) * STAGE);
        #pragma unroll
        for (int t = 0; t < 16; t++) {
            int isB = t >> 3;
            int row = srow + ((t & 7) << 4);
            const __half* src = isB
                ? pb + (long)(n0 + row) * ldb + kpos + (scs << 3)
                : pa + (long)(m0 + row) * lda + kpos + (scs << 3);
            uint32_t bo = (uint32_t)((row << 7) + (scs << 4));
            bo ^= (uint32_t)((row & 7) << 4);
            cpa16(sb + (uint32_t)(isB << 14) + bo, src);
        }
        asm volatile("cp.async.commit_group;" ::: "memory");
    };

    issue(0);
    issue(1);

    float acc[4][8][4] = {};
    int moff = (wid & 1) << 6;
    int noff = (wid >> 1) << 6;

    for (int c = 0; c < NC; c++) {
        if (c + 1 < NC) asm volatile("cp.async.wait_group 1;" ::: "memory");
        else            asm volatile("cp.async.wait_group 0;" ::: "memory");
        __syncthreads();
        if (c + 2 < NC) issue(c + 2);
        uint32_t sb = sbase + (uint32_t)((c % 3) * STAGE);

        #pragma unroll
        for (int ks = 0; ks < 4; ks++) {
            uint32_t afr[4][4];
            #pragma unroll
            for (int i = 0; i < 4; i++) {
                int row = moff + (i << 4) + (lane & 15);
                int colb = (ks << 5) + ((lane >> 4) << 4);
                uint32_t bo = (uint32_t)((row << 7) + colb) ^ (uint32_t)((row & 7) << 4);
                ldsm4(afr[i], sb + bo);
            }
            uint32_t bfr[8][2];
            #pragma unroll
            for (int j2 = 0; j2 < 4; j2++) {
                int row = noff + (j2 << 4) + ((lane >> 4) << 3) + (lane & 7);
                int colb = (ks << 5) + (((lane >> 3) & 1) << 4);
                uint32_t bo = (uint32_t)((row << 7) + colb) ^ (uint32_t)((row & 7) << 4);
                uint32_t r[4];
                ldsm4(r, sb + 16384u + bo);
                bfr[2 * j2][0] = r[0]; bfr[2 * j2][1] = r[1];
                bfr[2 * j2 + 1][0] = r[2]; bfr[2 * j2 + 1][1] = r[3];
            }
            #pragma unroll
            for (int i = 0; i < 4; i++)
                #pragma unroll
                for (int j = 0; j < 8; j++)
                    mma_f16(acc[i][j], afr[i], bfr[j]);
        }
    }

    int g = lane >> 2, t4 = lane & 3;
    if (MODE == 2) {
        __half* hi = (__half*)Cout + zm * cS1 + zd * cS2;
        __half* lo = (__half*)aux  + zm * cS1 + zd * cS2;
        #pragma unroll
        for (int i = 0; i < 4; i++) {
            int row0 = m0 + moff + (i << 4) + g;
            #pragma unroll
            for (int j = 0; j < 8; j++) {
                int col = n0 + noff + (j << 3) + (t4 << 1);
                #pragma unroll
                for (int rr = 0; rr < 2; rr++) {
                    long off = (long)(row0 + 8 * rr) * ldc + col;
                    float vx = acc[i][j][2 * rr], vy = acc[i][j][2 * rr + 1];
                    __half2 h = hl2(vx, vy);
                    __half2 l = hl2(vx - __half2float(h.x), vy - __half2float(h.y));
                    *reinterpret_cast<__half2*>(hi + off) = h;
                    *reinterpret_cast<__half2*>(lo + off) = l;
                }
            }
        }
    } else {
        float* C = (float*)Cout + zm * cS1 + zd * cS2 + (long)split * partStride;
        const float* bp = (MODE == 1) ? ((const float*)aux + zd * auxStride) : nullptr;
        #pragma unroll
        for (int i = 0; i < 4; i++) {
            int row0 = m0 + moff + (i << 4) + g;
            #pragma unroll
            for (int j = 0; j < 8; j++) {
                int col = n0 + noff + (j << 3) + (t4 << 1);
                float bx = 0.f, by = 0.f;
                if (MODE == 1) { float2 bb = *reinterpret_cast<const float2*>(bp + col); bx = bb.x; by = bb.y; }
                float2 o0 = make_float2(acc[i][j][0] + bx, acc[i][j][1] + by);
                float2 o1 = make_float2(acc[i][j][2] + bx, acc[i][j][3] + by);
                *reinterpret_cast<float2*>(&C[(long)row0 * ldc + col]) = o0;
                *reinterpret_cast<float2*>(&C[(long)(row0 + 8) * ldc + col]) = o1;
            }
        }
    }
}

__global__ void reduce_hl(const float* __restrict__ parts, long pstride, int nsplit,
                          __half* __restrict__ hi, __half* __restrict__ lo) {
    long i = ((long)blockIdx.x * blockDim.x + threadIdx.x) * 4;
    float4 s = *reinterpret_cast<const float4*>(parts + i);
    for (int p = 1; p < nsplit; p++) {
        float4 t = *reinterpret_cast<const float4*>(parts + p * pstride + i);
        s.x += t.x; s.y += t.y; s.z += t.z; s.w += t.w;
    }
    __half2 h0 = hl2(s.x, s.y), h1 = hl2(s.z, s.w);
    __half2 l0 = hl2(s.x - __half2float(h0.x), s.y - __half2float(h0.y));
    __half2 l1 = hl2(s.z - __half2float(h1.x), s.w - __half2float(h1.y));
    *reinterpret_cast<__half2*>(hi + i) = h0;
    *reinterpret_cast<__half2*>(hi + i + 2) = h1;
    *reinterpret_cast<__half2*>(lo + i) = l0;
    *reinterpret_cast<__half2*>(lo + i + 2) = l1;
}

__global__ void nt_epilogue(const float* __restrict__ parts, long pstride, int nsplit,
                            const float* __restrict__ alpha, const float* __restrict__ gamma,
                            const float* __restrict__ beta, const float* __restrict__ delta,
                            __half* __restrict__ hi, __half* __restrict__ lo) {
    long i = ((long)blockIdx.x * blockDim.x + threadIdx.x) * 4;
    int e = (int)(i & 511);
    int o3 = (int)((i >> 9) & 511);
    int b = (int)(i >> 18);
    float4 s = *reinterpret_cast<const float4*>(parts + i);
    for (int p = 1; p < nsplit; p++) {
        float4 t = *reinterpret_cast<const float4*>(parts + p * pstride + i);
        s.x += t.x; s.y += t.y; s.z += t.z; s.w += t.w;
    }
    #pragma unroll
    for (int h = 0; h < Hv; h++) {
        float be = beta[h * Ev + o3];
        float de = delta[(b * Hv + h) * Ev + o3];
        float4 al = *reinterpret_cast<const float4*>(alpha + (long)(b * Hv + h) * Ev + e);
        float4 ga = *reinterpret_cast<const float4*>(gamma + h * Ev + e);
        s.x += be * (al.x + (float)Sv * ga.x) + de * ga.x;
        s.y += be * (al.y + (float)Sv * ga.y) + de * ga.y;
        s.z += be * (al.z + (float)Sv * ga.z) + de * ga.z;
        s.w += be * (al.w + (float)Sv * ga.w) + de * ga.w;
    }
    const float invE = 1.0f / (float)Ev;
    s.x *= invE; s.y *= invE; s.z *= invE; s.w *= invE;
    __half2 h0 = hl2(s.x, s.y), h1 = hl2(s.z, s.w);
    __half2 l0 = hl2(s.x - __half2float(h0.x), s.y - __half2float(h0.y));
    __half2 l1 = hl2(s.z - __half2float(h1.x), s.w - __half2float(h1.y));
    *reinterpret_cast<__half2*>(hi + i) = h0;
    *reinterpret_cast<__half2*>(hi + i + 2) = h1;
    *reinterpret_cast<__half2*>(lo + i) = l0;
    *reinterpret_cast<__half2*>(lo + i + 2) = l1;
}

__global__ void conv_split(const float* __restrict__ src, __half* __restrict__ hi,
                           __half* __restrict__ lo) {
    long i = ((long)blockIdx.x * blockDim.x + threadIdx.x) * 4;
    float4 x = *reinterpret_cast<const float4*>(src + i);
    __half2 h0 = hl2(x.x, x.y), h1 = hl2(x.z, x.w);
    __half2 l0 = hl2(x.x - __half2float(h0.x), x.y - __half2float(h0.y));
    __half2 l1 = hl2(x.z - __half2float(h1.x), x.w - __half2float(h1.y));
    *reinterpret_cast<__half2*>(hi + i) = h0;
    *reinterpret_cast<__half2*>(hi + i + 2) = h1;
    *reinterpret_cast<__half2*>(lo + i) = l0;
    *reinterpret_cast<__half2*>(lo + i + 2) = l1;
}

__global__ void conv_hi(const float* __restrict__ src, __half* __restrict__ hi) {
    long i = ((long)blockIdx.x * blockDim.x + threadIdx.x) * 4;
    float4 x = *reinterpret_cast<const float4*>(src + i);
    *reinterpret_cast<__half2*>(hi + i) = hl2(x.x, x.y);
    *reinterpret_cast<__half2*>(hi + i + 2) = hl2(x.z, x.w);
}

__global__ void conv_tsplit(const float* __restrict__ src, __half* __restrict__ hi,
                            __half* __restrict__ lo,
                            int srcLd, long srcZ, int dstLd, long dstZ, int wlo) {
    __shared__ float tile[32][33];
    int zz = blockIdx.z;
    src += (long)zz * srcZ;
    long dz = (long)zz * dstZ;
    int k0 = blockIdx.x * 32, r0 = blockIdx.y * 32;
    int tx = threadIdx.x, ty = threadIdx.y;
    #pragma unroll
    for (int i = 0; i < 4; i++)
        tile[ty + 8 * i][tx] = src[(long)(k0 + ty + 8 * i) * srcLd + r0 + tx];
    __syncthreads();
    #pragma unroll
    for (int i = 0; i < 4; i++) {
        int r = r0 + ty + 8 * i, kk = k0 + tx;
        float x = tile[tx][ty + 8 * i];
        __half h = __float2half(x);
        hi[dz + (long)r * dstLd + kk] = h;
        if (wlo) lo[dz + (long)r * dstLd + kk] = __float2half(x - __half2float(h));
    }
}

// merged Wq + Wk transpose-split: grid (16, 16, 16)
__global__ void conv_t2(const float* __restrict__ Wq, const float* __restrict__ Wk,
                        __half* __restrict__ qhi, __half* __restrict__ qlo,
                        __half* __restrict__ khi, __half* __restrict__ klo) {
    __shared__ float tile[32][33];
    int zz = blockIdx.z;
    int h = zz & 7, which = zz >> 3;
    const float* src = (which ? Wk : Wq) + (long)h * EEv;
    __half* hi = (which ? khi : qhi) + (long)h * EEv;
    __half* lo = (which ? klo : qlo) + (long)h * EEv;
    int k0 = blockIdx.x * 32, r0 = blockIdx.y * 32;
    int tx = threadIdx.x, ty = threadIdx.y;
    #pragma unroll
    for (int i = 0; i < 4; i++)
        tile[ty + 8 * i][tx] = src[(long)(k0 + ty + 8 * i) * Ev + r0 + tx];
    __syncthreads();
    #pragma unroll
    for (int i = 0; i < 4; i++) {
        int r = r0 + ty + 8 * i, kk = k0 + tx;
        float x = tile[tx][ty + 8 * i];
        __half hh = __float2half(x);
        hi[(long)r * Ev + kk] = hh;
        lo[(long)r * Ev + kk] = __float2half(x - __half2float(hh));
    }
}

// merged k+v transpose (hi only): grid (64, 16, 8)
__global__ void conv_tkv(const float* __restrict__ k, const float* __restrict__ v,
                         __half* __restrict__ kT, __half* __restrict__ vT) {
    __shared__ float tile[32][33];
    int zz = blockIdx.z;
    int b = zz & 3, which = zz >> 2;
    const float* src = (which ? v : k) + (long)b * Sv * Ev;
    __half* dst = (which ? vT : kT) + (long)b * Ev * Sv;
    int k0 = blockIdx.x * 32, r0 = blockIdx.y * 32;
    int tx = threadIdx.x, ty = threadIdx.y;
    #pragma unroll
    for (int i = 0; i < 4; i++)
        tile[ty + 8 * i][tx] = src[(long)(k0 + ty + 8 * i) * Ev + r0 + tx];
    __syncthreads();
    #pragma unroll
    for (int i = 0; i < 4; i++)
        dst[(long)(r0 + ty + 8 * i) * Sv + k0 + tx] = __float2half(tile[tx][ty + 8 * i]);
}

__global__ void csum_part(const float* __restrict__ k, const float* __restrict__ v,
                          float* __restrict__ part) {
    int chunk = blockIdx.x, b = blockIdx.y, which = blockIdx.z, e = threadIdx.x;
    const float* src = (which ? v : k) + (long)b * Sv * Ev + (long)chunk * 128 * Ev + e;
    float s = 0.f;
    for (int i = 0; i < 128; i++) s += src[(long)i * Ev];
    part[(((long)which * Bv + b) * 16 + chunk) * Ev + e] = s;
}

__global__ void rowdot_aw(const float* __restrict__ Wk, const float* __restrict__ Wv,
                          const float* __restrict__ cspart,
                          float* __restrict__ a, float* __restrict__ w) {
    __shared__ float xs[Ev];
    int j = blockIdx.x;
    int which = (j >= 2048) ? 1 : 0;
    int jj = j - which * 2048;
    int zz = jj >> 6;
    int obase = (jj & 63) * 8;
    int b = zz >> 3, h = zz & 7;
    int tid = threadIdx.x;
    const float* cp = cspart + (((long)which * Bv + b) * 16) * Ev;
    #pragma unroll
    for (int t = 0; t < 2; t++) {
        int idx = tid + t * 256;
        float s = 0.f;
        #pragma unroll
        for (int i = 0; i < 16; i++) s += cp[(long)i * Ev + idx];
        xs[idx] = s;
    }
    __syncthreads();
    int wid = tid >> 5, lane = tid & 31;
    int o = obase + wid;
    const float* W = which ? Wv : Wk;
    const float* wr = W + (long)(h * Ev + o) * Ev;
    float s = 0.f;
    for (int e = lane; e < Ev; e += 32) s += wr[e] * xs[e];
    s = wredu(s);
    if (lane == 0) (which ? w : a)[(long)zz * Ev + o] = s;
}

__global__ void bias_pack(const __half* __restrict__ WqThi, const __half* __restrict__ WqTlo,
                          const __half* __restrict__ WkThi, const __half* __restrict__ WkTlo,
                          const float* __restrict__ Wo,
                          const float* __restrict__ a, const float* __restrict__ w,
                          const float* __restrict__ bq, const float* __restrict__ bk,
                          const float* __restrict__ bv,
                          float* __restrict__ alpha, float* __restrict__ gamma,
                          float* __restrict__ u, float* __restrict__ beta,
                          float* __restrict__ delta, float* __restrict__ s1,
                          float* __restrict__ s2) {
    int gw = (blockIdx.x * blockDim.x + threadIdx.x) >> 5, lane = threadIdx.x & 31;
    float s = 0.f;
    if (gw < 16384) {
        int e = gw & 511, zz = gw >> 9, h = zz & 7;
        long wofs = (long)h * EEv + (long)e * Ev;
        const float* xr = a + (long)zz * Ev;
        for (int o = lane; o < Ev; o += 32)
            s += (__half2float(WqThi[wofs + o]) + __half2float(WqTlo[wofs + o])) * xr[o];
        s = wredu(s);
        if (lane == 0) alpha[gw] = s;
    } else if (gw < 20480) {
        int g2 = gw - 16384, e = g2 & 511, h = g2 >> 9;
        long wofs = (long)h * EEv + (long)e * Ev;
        const float* xr = bk + (long)h * Ev;
        for (int o = lane; o < Ev; o += 32)
            s += (__half2float(WqThi[wofs + o]) + __half2float(WqTlo[wofs + o])) * xr[o];
        s = wredu(s);
        if (lane == 0) gamma[g2] = s;
    } else if (gw < 24576) {
        int g2 = gw - 20480, e = g2 & 511, h = g2 >> 9;
        long wofs = (long)h * EEv + (long)e * Ev;
        const float* xr = bq + (long)h * Ev;
        for (int o = lane; o < Ev; o += 32)
            s += (__half2float(WkThi[wofs + o]) + __half2float(WkTlo[wofs + o])) * xr[o];
        s = wredu(s);
        if (lane == 0) u[g2] = s;
    } else if (gw < 28672) {
        int g2 = gw - 24576, o3 = g2 & 511, h = g2 >> 9;
        const float* wr = Wo + (long)o3 * HEv + (long)h * Ev;
        const float* xr = bv + (long)h * Ev;
        for (int e = lane; e < Ev; e += 32) s += wr[e] * xr[e];
        s = wredu(s);
        if (lane == 0) beta[(long)h * Ev + o3] = s;
    } else if (gw < 45056) {
        int g2 = gw - 28672, o3 = g2 & 511, zz = g2 >> 9, h = zz & 7;
        const float* wr = Wo + (long)o3 * HEv + (long)h * Ev;
        const float* xr = w + (long)zz * Ev;
        for (int e = lane; e < Ev; e += 32) s += wr[e] * xr[e];
        s = wredu(s);
        if (lane == 0) delta[(long)zz * Ev + o3] = s;
    } else if (gw < 45096) {
        int idx = gw - 45056;
        const float* xa;
        const float* xb;
        if (idx < 32) { xa = bq + (idx & 7) * Ev; xb = a + (long)idx * Ev; }
        else          { xa = bq + (idx - 32) * Ev; xb = bk + (idx - 32) * Ev; }
        for (int o = lane; o < Ev; o += 32) s += xa[o] * xb[o];
        s = wredu(s);
        if (lane == 0) { if (idx < 32) s1[idx] = s; else s2[idx - 32] = s; }
    }
}

__global__ void colmv_part(const __half* __restrict__ Ghi, const __half* __restrict__ Glo,
                           const float* __restrict__ u, float* __restrict__ pp) {
    int zz = blockIdx.x, chunk = blockIdx.y, tid = threadIdx.x;
    int b = zz >> 3, h = zz & (Hv - 1);
    __shared__ float us[64];
    if (tid < 64) us[tid] = u[h * Ev + chunk * 64 + tid];
    __syncthreads();
    const __half* gh = Ghi + (long)b * EEv + (long)chunk * 64 * Ev;
    const __half* gl = Glo + (long)b * EEv + (long)chunk * 64 * Ev;
    float acc = 0.f;
    #pragma unroll 4
    for (int i = 0; i < 64; i++) {
        long idx = (long)i * Ev + tid;
        acc += us[i] * (__half2float(gh[idx]) + __half2float(gl[idx]));
    }
    pp[((long)zz * 8 + chunk) * Ev + tid] = acc;
}

__global__ void sigma_f(const float* __restrict__ pp, const float* __restrict__ Wv,
                        float* __restrict__ sigma) {
    __shared__ float ps[Ev];
    int j = blockIdx.x;
    int zz = j >> 6;
    int obase = (j & 63) * 8;
    int h = zz & 7;
    int tid = threadIdx.x;
    const float* q = pp + (long)zz * 8 * Ev;
    #pragma unroll
    for (int t = 0; t < 2; t++) {
        int idx = tid + t * 256;
        float s = 0.f;
        #pragma unroll
        for (int i = 0; i < 8; i++) s += q[(long)i * Ev + idx];
        ps[idx] = s;
    }
    __syncthreads();
    int wid = tid >> 5, lane = tid & 31;
    int o = obase + wid;
    const float* wr = Wv + (long)(h * Ev + o) * Ev;
    float s = 0.f;
    for (int o2 = lane; o2 < Ev; o2 += 32) s += wr[o2] * ps[o2];
    s = wredu(s);
    if (lane == 0) sigma[(long)zz * Ev + o] = s;
}

__global__ void cvec_f(const float* __restrict__ sigma, const float* __restrict__ s1,
                       const float* __restrict__ s2, const float* __restrict__ bv,
                       const float* __restrict__ w, const float* __restrict__ Wo,
                       const float* __restrict__ bo, float* __restrict__ c) {
    int gw = (blockIdx.x * blockDim.x + threadIdx.x) >> 5, lane = threadIdx.x & 31;
    int o3 = gw & (Ev - 1), b = gw >> 9;
    const float* wr = Wo + (long)o3 * HEv;
    float s = 0.f;
    for (int f = lane; f < HEv; f += 32) {
        int h = f >> 9, o2 = f & 511;
        int zz = b * Hv + h;
        float bvv = bv[h * Ev + o2];
        float tau = sigma[(long)zz * Ev + o2] + s1[zz] * bvv
                  + s2[h] * (w[(long)zz * Ev + o2] + (float)Sv * bvv);
        s += wr[f] * tau;
    }
    s = wredu(s);
    if (lane == 0) c[gw] = s * (1.0f / (float)Ev) + bo[o3];
}

extern "C" void kernel_launch(void* const* d_in, const int* in_sizes, int n_in,
                              void* d_out, int out_size) {
    const float* q  = (const float*)d_in[0];
    const float* k  = (const float*)d_in[1];
    const float* v  = (const float*)d_in[2];
    const float* Wq = (const float*)d_in[3];
    const float* bq = (const float*)d_in[4];
    const float* Wk = (const float*)d_in[5];
    const float* bk = (const float*)d_in[6];
    const float* Wv = (const float*)d_in[7];
    const float* bv = (const float*)d_in[8];
    const float* Wo = (const float*)d_in[9];
    const float* bo = (const float*)d_in[10];
    float* out = (float*)d_out;

    float *Tp, *cspart, *pp, *a, *w, *alpha, *gamma, *beta, *delta, *u, *sigma, *s1, *s2, *c;
    cudaGetSymbolAddress((void**)&Tp, g_T);
    cudaGetSymbolAddress((void**)&cspart, g_cspart);
    cudaGetSymbolAddress((void**)&pp, g_pp);
    cudaGetSymbolAddress((void**)&a, g_a);
    cudaGetSymbolAddress((void**)&w, g_w);
    cudaGetSymbolAddress((void**)&alpha, g_alpha);
    cudaGetSymbolAddress((void**)&gamma, g_gamma);
    cudaGetSymbolAddress((void**)&beta, g_beta);
    cudaGetSymbolAddress((void**)&delta, g_delta);
    cudaGetSymbolAddress((void**)&u, g_u);
    cudaGetSymbolAddress((void**)&sigma, g_sigma);
    cudaGetSymbolAddress((void**)&s1, g_s1);
    cudaGetSymbolAddress((void**)&s2, g_s2);
    cudaGetSymbolAddress((void**)&c, g_c);

    __half *kT, *vT, *bWqT, *bWkT, *bWvT, *bWo, *bG, *bU, *bV, *bX, *bq16, *bNT;
    cudaGetSymbolAddress((void**)&kT, c_kT);
    cudaGetSymbolAddress((void**)&vT, c_vT);
    cudaGetSymbolAddress((void**)&bWqT, c_WqT);
    cudaGetSymbolAddress((void**)&bWkT, c_WkT);
    cudaGetSymbolAddress((void**)&bWvT, c_WvT);
    cudaGetSymbolAddress((void**)&bWo, c_Wo);
    cudaGetSymbolAddress((void**)&bG, c_G);
    cudaGetSymbolAddress((void**)&bU, c_U);
    cudaGetSymbolAddress((void**)&bV, c_V);
    cudaGetSymbolAddress((void**)&bX, c_X);
    cudaGetSymbolAddress((void**)&bq16, c_q);
    cudaGetSymbolAddress((void**)&bNT, c_NT);

    static cudaStream_t sW = nullptr, sP = nullptr;
    static cudaEvent_t evRoot, evWc, evV, evWU, evG, evB, evC;
    if (!sW) {
        cudaStreamCreateWithFlags(&sW, cudaStreamNonBlocking);
        cudaStreamCreateWithFlags(&sP, cudaStreamNonBlocking);
        cudaEventCreateWithFlags(&evRoot, cudaEventDisableTiming);
        cudaEventCreateWithFlags(&evWc, cudaEventDisableTiming);
        cudaEventCreateWithFlags(&evV, cudaEventDisableTiming);
        cudaEventCreateWithFlags(&evWU, cudaEventDisableTiming);
        cudaEventCreateWithFlags(&evG, cudaEventDisableTiming);
        cudaEventCreateWithFlags(&evB, cudaEventDisableTiming);
        cudaEventCreateWithFlags(&evC, cudaEventDisableTiming);
        cudaFuncSetAttribute(tgemm<0>, cudaFuncAttributeMaxDynamicSharedMemorySize, SMEM_DYN);
        cudaFuncSetAttribute(tgemm<1>, cudaFuncAttributeMaxDynamicSharedMemorySize, SMEM_DYN);
        cudaFuncSetAttribute(tgemm<2>, cudaFuncAttributeMaxDynamicSharedMemorySize, SMEM_DYN);
    }

    const long ES = (long)Ev * Sv, EE = EEv, SE = (long)Sv * Ev, EHE = (long)Ev * HEv;
    const long hKT = (long)Bv * ES, hW = (long)Hv * EEv, hWo = (long)Ev * HEv;
    const long hG = (long)Bv * EEv, hU = (long)Ev * HEv, hV = (long)Hv * EEv;
    const long hX = (long)Bv * Ev * HEv, hq = (long)Bv * SE, hNT = (long)Bv * EEv;
    const long PART = (long)Bv * EEv;

    dim3 tb(32, 8);

    cudaEventRecord(evRoot, 0);

    // ---- stream W: V first (2-term), then U (2-term) ----
    cudaStreamWaitEvent(sW, evRoot, 0);
    conv_tsplit<<<dim3(16, 16, Hv), tb, 0, sW>>>(Wv, bWvT, bWvT + hW, Ev, EE, Ev, EE, 1);
    conv_split<<<2048, 256, 0, sW>>>(Wo, bWo, bWo + hWo);
    tgemm<2><<<dim3(4, 4, Hv), 128, SMEM_DYN, sW>>>(
        bWo, bWo + hWo, bWvT, bWvT + hW, bV, bV + hV,
        Ev, HEv, Ev, Ev, Hv, (long)Ev, 0, EE, 0, EE, 0, 0, 1, 0, 2);
    cudaEventRecord(evV, sW);
    conv_t2<<<dim3(16, 16, 16), tb, 0, sW>>>(Wq, Wk, bWqT, bWqT + hW, bWkT, bWkT + hW);
    cudaEventRecord(evWc, sW);
    tgemm<2><<<dim3(4, 4, Hv), 128, SMEM_DYN, sW>>>(
        bWqT, bWqT + hW, bWkT, bWkT + hW, bU, bU + hU,
        Ev, Ev, Ev, HEv, Hv, EE, 0, EE, 0, (long)Ev, 0, 0, 1, 0, 2);
    cudaEventRecord(evWU, sW);

    // ---- stream P: colsum partials, fused a/w, q conv ----
    cudaStreamWaitEvent(sP, evRoot, 0);
    csum_part<<<dim3(16, Bv, 2), Ev, 0, sP>>>(k, v, cspart);
    rowdot_aw<<<4096, 256, 0, sP>>>(Wk, Wv, cspart, a, w);
    conv_hi<<<4096, 256, 0, sP>>>(q, bq16);

    // ---- main stream: merged k/v transpose, G (1-term, split-2) ----
    conv_tkv<<<dim3(64, 16, Bv * 2), tb>>>(k, v, kT, vT);
    tgemm<0><<<dim3(4, 4, Bv * 2), 128, SMEM_DYN>>>(
        kT, kT + hKT, vT, vT + hKT, Tp, nullptr,
        Sv, Sv, Sv, Ev, 1, 0, ES, 0, ES, 0, EE, 0, 2, PART, 1);
    reduce_hl<<<1024, 256>>>(Tp, PART, 2, bG, bG + hG);
    cudaEventRecord(evG, 0);

    // ---- stream P: fused bias kernel, then G-dependent tail ----
    cudaStreamWaitEvent(sP, evWc, 0);
    bias_pack<<<5637, 256, 0, sP>>>(bWqT, bWqT + hW, bWkT, bWkT + hW, Wo,
                                    a, w, bq, bk, bv,
                                    alpha, gamma, u, beta, delta, s1, s2);
    cudaEventRecord(evB, sP);
    cudaStreamWaitEvent(sP, evG, 0);
    colmv_part<<<dim3(32, 8), Ev, 0, sP>>>(bG, bG + hG, u, pp);
    sigma_f<<<2048, 256, 0, sP>>>(pp, Wv, sigma);
    cvec_f<<<256, 256, 0, sP>>>(sigma, s1, s2, bv, w, Wo, bo, c);
    cudaEventRecord(evC, sP);

    // ---- main stream: X (1-term), NT (1-term, split-2), epilogue, out (1-term) ----
    cudaStreamWaitEvent(0, evV, 0);
    tgemm<2><<<dim3(4, 4, Bv * Hv), 128, SMEM_DYN>>>(
        bV, bV + hV, bG, bG + hG, bX, bX + hX,
        Ev, Ev, Ev, HEv, Hv, EE, 0, 0, EE, (long)Ev, EHE, 0, 1, 0, 1);
    cudaStreamWaitEvent(0, evWU, 0);
    tgemm<0><<<dim3(4, 4, Bv * 2), 128, SMEM_DYN>>>(
        bX, bX + hX, bU, bU + hU, Tp, nullptr,
        HEv, HEv, HEv, Ev, 1, 0, EHE, 0, 0, 0, EE, 0, 2, PART, 1);
    cudaStreamWaitEvent(0, evB, 0);
    nt_epilogue<<<1024, 256>>>(Tp, PART, 2, alpha, gamma, beta, delta, bNT, bNT + hNT);
    cudaStreamWaitEvent(0, evC, 0);
    tgemm<1><<<dim3(4, 16, Bv), 128, SMEM_DYN>>>(
        bq16, bq16 + hq, bNT, bNT + hNT, out, c,
        Ev, Ev, Ev, Ev, 1, 0, SE, 0, EE, 0, SE, (long)Ev, 1, 0, 1);
}